// round 1
// baseline (speedup 1.0000x reference)
#include <cuda_runtime.h>
#include <math.h>

#define WSD 12
#define NTOK 144
#define CDIM 384
#define NH 12
#define HD 32
#define NWIN 4
#define BWIN 512
#define MROWS (BWIN*NTOK)   // 73728

// ---------------- scratch (no allocations allowed) ----------------
__device__ float g_q[(size_t)BWIN*NH*NTOK*HD];
__device__ float g_k[(size_t)BWIN*NH*NTOK*HD];
__device__ float g_v[(size_t)BWIN*NH*NTOK*HD];
__device__ float g_attout[(size_t)MROWS*CDIM];
__device__ float g_tab[529*NH];
__device__ float g_bias[NH*NTOK*NTOK];

// ---------------- CPB-MLP bias table: (529, 12) ----------------
__global__ void bias_tab_kernel(const float* __restrict__ w1,
                                const float* __restrict__ b1,
                                const float* __restrict__ w2) {
    __shared__ float hid[512];
    int t = blockIdx.x;          // 0..528
    int ti = t / 23, tj = t % 23;
    float ra = (float)(ti - 11) * (12.0f / 11.0f);
    float rb = (float)(tj - 11) * (12.0f / 11.0f);
    float sa = (ra > 0.f) ? 1.f : ((ra < 0.f) ? -1.f : 0.f);
    float sb = (rb > 0.f) ? 1.f : ((rb < 0.f) ? -1.f : 0.f);
    float t0 = sa * log2f(fabsf(ra) + 1.0f) * (1.0f / 3.0f);
    float t1 = sb * log2f(fabsf(rb) + 1.0f) * (1.0f / 3.0f);
    int j = threadIdx.x;         // 0..511
    hid[j] = fmaxf(t0 * w1[2*j] + t1 * w1[2*j+1] + b1[j], 0.0f);
    __syncthreads();
    if (j < NH) {
        float s = 0.f;
        const float* wr = w2 + j * 512;
        #pragma unroll 8
        for (int q = 0; q < 512; q++) s += hid[q] * wr[q];
        g_tab[t * NH + j] = s;
    }
}

// ---------------- gather + 16*sigmoid into (h, n, m) ----------------
__global__ void bias_gather_kernel() {
    int g = blockIdx.x * blockDim.x + threadIdx.x;
    if (g >= NH * NTOK * NTOK) return;
    int h = g / (NTOK * NTOK);
    int r = g % (NTOK * NTOK);
    int n = r / NTOK, m = r % NTOK;
    int dr = n / WSD - m / WSD + 11;
    int dc = n % WSD - m % WSD + 11;
    float v = g_tab[(dr * 23 + dc) * NH + h];
    g_bias[g] = 16.0f / (1.0f + expf(-v));
}

// ---------------- QKV SGEMM: (73728,384) x (1152,384)^T -> scatter q/k/v ----------------
__global__ __launch_bounds__(256) void qkv_gemm_kernel(
    const float* __restrict__ x, const float* __restrict__ w,
    const float* __restrict__ bias) {
    const int K = CDIM;
    __shared__ float As[8][132];
    __shared__ float Bs[8][132];
    int m0 = blockIdx.y * 128, n0 = blockIdx.x * 128;
    int tid = threadIdx.x;
    int lrow = tid >> 1, lk = (tid & 1) * 4;
    int ty = tid >> 4, tx = tid & 15;
    float acc[8][8] = {};

    for (int k0 = 0; k0 < K; k0 += 8) {
        float4 a4 = *(const float4*)(x + (size_t)(m0 + lrow) * K + k0 + lk);
        float4 b4 = *(const float4*)(w + (size_t)(n0 + lrow) * K + k0 + lk);
        As[lk+0][lrow] = a4.x; As[lk+1][lrow] = a4.y;
        As[lk+2][lrow] = a4.z; As[lk+3][lrow] = a4.w;
        Bs[lk+0][lrow] = b4.x; Bs[lk+1][lrow] = b4.y;
        Bs[lk+2][lrow] = b4.z; Bs[lk+3][lrow] = b4.w;
        __syncthreads();
        #pragma unroll
        for (int kk = 0; kk < 8; kk++) {
            float a[8], b[8];
            #pragma unroll
            for (int i = 0; i < 8; i++) a[i] = As[kk][ty*8+i];
            #pragma unroll
            for (int j = 0; j < 8; j++) b[j] = Bs[kk][tx*8+j];
            #pragma unroll
            for (int i = 0; i < 8; i++)
                #pragma unroll
                for (int j = 0; j < 8; j++)
                    acc[i][j] += a[i] * b[j];
        }
        __syncthreads();
    }

    #pragma unroll
    for (int i = 0; i < 8; i++) {
        int row = m0 + ty*8 + i;
        int bb = row / NTOK, nn = row % NTOK;
        #pragma unroll
        for (int j = 0; j < 8; j++) {
            int col = n0 + tx*8 + j;
            float v = acc[i][j] + bias[col];
            int which = col / CDIM, rem = col % CDIM;
            int hh = rem >> 5, dd = rem & 31;
            float* dst = (which == 0) ? g_q : ((which == 1) ? g_k : g_v);
            dst[(((size_t)bb * NH + hh) * NTOK + nn) * HD + dd] = v;
        }
    }
}

// ---------------- fused attention: one block per (b,h) ----------------
__global__ __launch_bounds__(256, 1) void attn_kernel(
    const float* __restrict__ mask, const float* __restrict__ logit_scale) {
    extern __shared__ float sm[];
    float* qs   = sm;                 // 144*33 = 4752
    float* ks   = qs + 4752;
    float* vs   = ks + 4752;
    float* Ssm  = vs + 4752;          // 144*145 = 20880
    float* red  = Ssm + 20880;        // 144*16 = 2304
    float* qinv = red + 2304;         // 144
    float* kinv = qinv + 144;         // 144
    float* rmax = kinv + 144;         // 144
    float* rsum = rmax + 144;         // 144

    int bh = blockIdx.x;
    int b = bh / NH, h = bh % NH;
    int w = b & 3;                    // b % NWIN
    const float* gq = g_q + (size_t)bh * NTOK * HD;
    const float* gk = g_k + (size_t)bh * NTOK * HD;
    const float* gv = g_v + (size_t)bh * NTOK * HD;
    int tid = threadIdx.x;

    for (int i = tid; i < NTOK * HD; i += 256) {
        int n = i >> 5, d = i & 31;
        qs[n*33+d] = gq[i];
        ks[n*33+d] = gk[i];
        vs[n*33+d] = gv[i];
    }
    __syncthreads();

    if (tid < NTOK) {
        float s = 0.f, t = 0.f;
        #pragma unroll
        for (int d = 0; d < 32; d++) {
            float a = qs[tid*33+d]; s += a * a;
            float c = ks[tid*33+d]; t += c * c;
        }
        qinv[tid] = 1.0f / fmaxf(sqrtf(s), 1e-12f);
        kinv[tid] = 1.0f / fmaxf(sqrtf(t), 1e-12f);
    }
    __syncthreads();

    float sc = expf(fminf(logit_scale[h], 4.6051702f));  // ln(100)

    int ty = tid >> 4, tx = tid & 15;
    float acc[9][9] = {};
    const float* qrow = qs + (ty * 9) * 33;
    const float* krow = ks + (tx * 9) * 33;
    #pragma unroll 4
    for (int kk = 0; kk < 32; kk++) {
        float a[9], c[9];
        #pragma unroll
        for (int i = 0; i < 9; i++) a[i] = qrow[i*33+kk];
        #pragma unroll
        for (int j = 0; j < 9; j++) c[j] = krow[j*33+kk];
        #pragma unroll
        for (int i = 0; i < 9; i++)
            #pragma unroll
            for (int j = 0; j < 9; j++)
                acc[i][j] += a[i] * c[j];
    }

    const float* bi = g_bias + (size_t)h * NTOK * NTOK;
    const float* mk = mask + (size_t)w * NTOK * NTOK;
    #pragma unroll
    for (int i = 0; i < 9; i++) {
        int r = ty*9 + i;
        float qv = qinv[r] * sc;
        float mx = -1e30f;
        #pragma unroll
        for (int j = 0; j < 9; j++) {
            int c = tx*9 + j;
            float v = acc[i][j] * qv * kinv[c] + bi[r*NTOK+c] + mk[r*NTOK+c];
            acc[i][j] = v;
            mx = fmaxf(mx, v);
        }
        red[r*16+tx] = mx;
    }
    __syncthreads();
    if (tid < NTOK) {
        float mx = -1e30f;
        #pragma unroll
        for (int t2 = 0; t2 < 16; t2++) mx = fmaxf(mx, red[tid*16+t2]);
        rmax[tid] = mx;
    }
    __syncthreads();

    #pragma unroll
    for (int i = 0; i < 9; i++) {
        int r = ty*9 + i;
        float mx = rmax[r];
        float s = 0.f;
        #pragma unroll
        for (int j = 0; j < 9; j++) {
            float e = __expf(acc[i][j] - mx);
            Ssm[r*145 + tx*9 + j] = e;
            s += e;
        }
        red[r*16+tx] = s;
    }
    __syncthreads();
    if (tid < NTOK) {
        float s = 0.f;
        #pragma unroll
        for (int t2 = 0; t2 < 16; t2++) s += red[tid*16+t2];
        rsum[tid] = 1.0f / s;
    }
    __syncthreads();

    // PV: out[r][d], d = tx and tx+16
    float o[9][2] = {};
    for (int m = 0; m < NTOK; m++) {
        float p[9];
        #pragma unroll
        for (int i = 0; i < 9; i++) p[i] = Ssm[(ty*9+i)*145 + m];
        float v0 = vs[m*33 + tx];
        float v1 = vs[m*33 + tx + 16];
        #pragma unroll
        for (int i = 0; i < 9; i++) {
            o[i][0] += p[i] * v0;
            o[i][1] += p[i] * v1;
        }
    }
    float* oo = g_attout + ((size_t)b * NTOK) * CDIM + h * HD;
    #pragma unroll
    for (int i = 0; i < 9; i++) {
        int r = ty*9 + i;
        float ri = rsum[r];
        oo[(size_t)r*CDIM + tx]      = o[i][0] * ri;
        oo[(size_t)r*CDIM + tx + 16] = o[i][1] * ri;
    }
}

// ---------------- proj SGEMM: (73728,384) x (384,384)^T + b -> out ----------------
__global__ __launch_bounds__(256) void proj_gemm_kernel(
    const float* __restrict__ w, const float* __restrict__ bias,
    float* __restrict__ out) {
    const int K = CDIM;
    __shared__ float As[8][132];
    __shared__ float Bs[8][132];
    int m0 = blockIdx.y * 128, n0 = blockIdx.x * 128;
    int tid = threadIdx.x;
    int lrow = tid >> 1, lk = (tid & 1) * 4;
    int ty = tid >> 4, tx = tid & 15;
    float acc[8][8] = {};

    const float* x = g_attout;
    for (int k0 = 0; k0 < K; k0 += 8) {
        float4 a4 = *(const float4*)(x + (size_t)(m0 + lrow) * K + k0 + lk);
        float4 b4 = *(const float4*)(w + (size_t)(n0 + lrow) * K + k0 + lk);
        As[lk+0][lrow] = a4.x; As[lk+1][lrow] = a4.y;
        As[lk+2][lrow] = a4.z; As[lk+3][lrow] = a4.w;
        Bs[lk+0][lrow] = b4.x; Bs[lk+1][lrow] = b4.y;
        Bs[lk+2][lrow] = b4.z; Bs[lk+3][lrow] = b4.w;
        __syncthreads();
        #pragma unroll
        for (int kk = 0; kk < 8; kk++) {
            float a[8], b[8];
            #pragma unroll
            for (int i = 0; i < 8; i++) a[i] = As[kk][ty*8+i];
            #pragma unroll
            for (int j = 0; j < 8; j++) b[j] = Bs[kk][tx*8+j];
            #pragma unroll
            for (int i = 0; i < 8; i++)
                #pragma unroll
                for (int j = 0; j < 8; j++)
                    acc[i][j] += a[i] * b[j];
        }
        __syncthreads();
    }

    #pragma unroll
    for (int i = 0; i < 8; i++) {
        int row = m0 + ty*8 + i;
        #pragma unroll
        for (int j = 0; j < 8; j++) {
            int col = n0 + tx*8 + j;
            out[(size_t)row * CDIM + col] = acc[i][j] + bias[col];
        }
    }
}

// ---------------- launcher ----------------
extern "C" void kernel_launch(void* const* d_in, const int* in_sizes, int n_in,
                              void* d_out, int out_size) {
    const float* x           = (const float*)d_in[0];
    const float* mask        = (const float*)d_in[1];
    const float* qkv_w       = (const float*)d_in[2];
    const float* qkv_b       = (const float*)d_in[3];
    const float* logit_scale = (const float*)d_in[4];
    const float* cpb_w1      = (const float*)d_in[5];
    const float* cpb_b1      = (const float*)d_in[6];
    const float* cpb_w2      = (const float*)d_in[7];
    const float* proj_w      = (const float*)d_in[8];
    const float* proj_b      = (const float*)d_in[9];
    float* out = (float*)d_out;

    const int smem_attn = (4752*3 + 20880 + 2304 + 4*144) * 4;  // 152064 B
    cudaFuncSetAttribute(attn_kernel, cudaFuncAttributeMaxDynamicSharedMemorySize, smem_attn);

    bias_tab_kernel<<<529, 512>>>(cpb_w1, cpb_b1, cpb_w2);
    bias_gather_kernel<<<(NH*NTOK*NTOK + 255)/256, 256>>>();
    qkv_gemm_kernel<<<dim3(9, 576), 256>>>(x, qkv_w, qkv_b);
    attn_kernel<<<BWIN*NH, 256, smem_attn>>>(mask, logit_scale);
    proj_gemm_kernel<<<dim3(3, 576), 256>>>(proj_w, proj_b, out);
}

// round 3
// speedup vs baseline: 1.6895x; 1.6895x over previous
#include <cuda_runtime.h>
#include <cuda_bf16.h>
#include <math.h>
#include <stdint.h>

#define WSD 12
#define NTOK 144
#define CDIM 384
#define NH 12
#define HD 32
#define NWIN 4
#define BWIN 512
#define MROWS (BWIN*NTOK)   // 73728

// ---------------- scratch (no allocations allowed) ----------------
__device__ float g_q[(size_t)BWIN*NH*NTOK*HD];
__device__ float g_k[(size_t)BWIN*NH*NTOK*HD];
__device__ float g_v[(size_t)BWIN*NH*NTOK*HD];
__device__ __nv_bfloat16 g_xhi[(size_t)MROWS*CDIM];
__device__ __nv_bfloat16 g_xlo[(size_t)MROWS*CDIM];
__device__ __nv_bfloat16 g_aohi[(size_t)MROWS*CDIM];
__device__ __nv_bfloat16 g_aolo[(size_t)MROWS*CDIM];
__device__ __nv_bfloat16 g_wqhi[3*CDIM*CDIM];
__device__ __nv_bfloat16 g_wqlo[3*CDIM*CDIM];
__device__ __nv_bfloat16 g_wphi[CDIM*CDIM];
__device__ __nv_bfloat16 g_wplo[CDIM*CDIM];
__device__ float g_tab[529*NH];
__device__ float g_bias[NH*NTOK*NTOK];

// ================= helpers =================
__device__ __forceinline__ uint32_t smem_u32(const void* p) {
    uint32_t a;
    asm("{ .reg .u64 t; cvta.to.shared.u64 t, %1; cvt.u32.u64 %0, t; }" : "=r"(a) : "l"(p));
    return a;
}
__device__ __forceinline__ void ldsm4(uint32_t* r, uint32_t addr) {
    asm volatile("ldmatrix.sync.aligned.m8n8.x4.shared.b16 {%0,%1,%2,%3}, [%4];"
        : "=r"(r[0]), "=r"(r[1]), "=r"(r[2]), "=r"(r[3]) : "r"(addr));
}
__device__ __forceinline__ void mma16816(float* c, const uint32_t* a, const uint32_t* b) {
    asm volatile("mma.sync.aligned.m16n8k16.row.col.f32.bf16.bf16.f32 "
        "{%0,%1,%2,%3}, {%4,%5,%6,%7}, {%8,%9}, {%0,%1,%2,%3};"
        : "+f"(c[0]), "+f"(c[1]), "+f"(c[2]), "+f"(c[3])
        : "r"(a[0]), "r"(a[1]), "r"(a[2]), "r"(a[3]), "r"(b[0]), "r"(b[1]));
}
__device__ __forceinline__ void split1(float v, __nv_bfloat16& h, __nv_bfloat16& l) {
    h = __float2bfloat16(v);
    l = __float2bfloat16(v - __bfloat162float(h));
}

// ---------------- fp32 -> bf16 hi/lo split ----------------
__global__ void conv_split_kernel(const float* __restrict__ src,
                                  __nv_bfloat16* __restrict__ hi,
                                  __nv_bfloat16* __restrict__ lo, int n4) {
    int i = blockIdx.x * blockDim.x + threadIdx.x;
    if (i >= n4) return;
    float4 v = ((const float4*)src)[i];
    __nv_bfloat16 h0, l0, h1, l1, h2, l2, h3, l3;
    split1(v.x, h0, l0); split1(v.y, h1, l1);
    split1(v.z, h2, l2); split1(v.w, h3, l3);
    uint2 ph, pl;
    ph.x = (uint32_t)__bfloat16_as_ushort(h0) | ((uint32_t)__bfloat16_as_ushort(h1) << 16);
    ph.y = (uint32_t)__bfloat16_as_ushort(h2) | ((uint32_t)__bfloat16_as_ushort(h3) << 16);
    pl.x = (uint32_t)__bfloat16_as_ushort(l0) | ((uint32_t)__bfloat16_as_ushort(l1) << 16);
    pl.y = (uint32_t)__bfloat16_as_ushort(l2) | ((uint32_t)__bfloat16_as_ushort(l3) << 16);
    *(uint2*)(hi + 4*(size_t)i) = ph;
    *(uint2*)(lo + 4*(size_t)i) = pl;
}

// ================= mma.sync GEMM =================
// C[M,Ntot] = A[M,384] @ W[Ntot,384]^T + bias.  CTA tile 128x128, warp tile 64x32.
// 3-product bf16 split into shared fp32 accumulators.
#define LDSB 144            // smem row stride bytes (72 bf16)
#define A_HI 0
#define A_LO 18432
#define B_HI 36864
#define B_LO 55296
#define GEMM_SMEM 73728

__global__ __launch_bounds__(256, 1)
void mma_gemm_kernel(const __nv_bfloat16* __restrict__ Ahi,
                     const __nv_bfloat16* __restrict__ Alo,
                     const __nv_bfloat16* __restrict__ Bhi,
                     const __nv_bfloat16* __restrict__ Blo,
                     const float* __restrict__ bias,
                     float* __restrict__ outp,
                     int qkv_mode)
{
    extern __shared__ char smem[];
    uint32_t sb = smem_u32(smem);
    int tid = threadIdx.x;
    int wid = tid >> 5, lane = tid & 31;
    int wm = wid & 1, wn = wid >> 1;
    int m0 = blockIdx.y * 128, n0 = blockIdx.x * 128;

    float acc[4][4][4] = {};

    // per-lane ldmatrix address components
    uint32_t aoff = (uint32_t)((wm*64 + (lane & 15)) * LDSB + (((lane >> 4) & 1) << 4));
    uint32_t boff = (uint32_t)((wn*32 + (lane & 7) + ((lane & 16) >> 1)) * LDSB + ((lane & 8) << 1));

    for (int c = 0; c < 6; c++) {
        int kc = c * 64;
        // fill: each matrix 128 rows x 64 bf16 (8 uint4 per row)
        #pragma unroll
        for (int i = 0; i < 4; i++) {
            int f = tid + (i << 8);
            int row = f >> 3, c8 = (f & 7) << 3;
            size_t ga = (size_t)(m0 + row) * CDIM + kc + c8;
            size_t gb = (size_t)(n0 + row) * CDIM + kc + c8;
            uint32_t so = (uint32_t)(row * LDSB + (c8 << 1));
            *(uint4*)(smem + A_HI + so) = *(const uint4*)(Ahi + ga);
            *(uint4*)(smem + A_LO + so) = *(const uint4*)(Alo + ga);
            *(uint4*)(smem + B_HI + so) = *(const uint4*)(Bhi + gb);
            *(uint4*)(smem + B_LO + so) = *(const uint4*)(Blo + gb);
        }
        __syncthreads();

        #pragma unroll
        for (int ks = 0; ks < 4; ks++) {
            uint32_t ahi[4][4], alo[4][4], bhi[2][4], blo[2][4];
            uint32_t kb = (uint32_t)(ks << 5);
            #pragma unroll
            for (int mt = 0; mt < 4; mt++) {
                ldsm4(ahi[mt], sb + A_HI + aoff + mt*(16*LDSB) + kb);
                ldsm4(alo[mt], sb + A_LO + aoff + mt*(16*LDSB) + kb);
            }
            #pragma unroll
            for (int tp = 0; tp < 2; tp++) {
                ldsm4(bhi[tp], sb + B_HI + boff + tp*(16*LDSB) + kb);
                ldsm4(blo[tp], sb + B_LO + boff + tp*(16*LDSB) + kb);
            }
            #pragma unroll
            for (int mt = 0; mt < 4; mt++) {
                #pragma unroll
                for (int tp = 0; tp < 2; tp++) {
                    mma16816(acc[mt][2*tp],   ahi[mt], &bhi[tp][0]);
                    mma16816(acc[mt][2*tp+1], ahi[mt], &bhi[tp][2]);
                    mma16816(acc[mt][2*tp],   ahi[mt], &blo[tp][0]);
                    mma16816(acc[mt][2*tp+1], ahi[mt], &blo[tp][2]);
                    mma16816(acc[mt][2*tp],   alo[mt], &bhi[tp][0]);
                    mma16816(acc[mt][2*tp+1], alo[mt], &bhi[tp][2]);
                }
            }
        }
        __syncthreads();
    }

    // epilogue
    int colw = n0 + wn * 32;
    float* dstq = nullptr;
    int which = 0, h = 0;
    if (qkv_mode) {
        which = colw / CDIM;
        int rem = colw - which * CDIM;
        h = rem >> 5;
        dstq = (which == 0) ? g_q : ((which == 1) ? g_k : g_v);
    }
    #pragma unroll
    for (int mt = 0; mt < 4; mt++) {
        int r0 = m0 + wm*64 + mt*16 + (lane >> 2);
        #pragma unroll
        for (int half = 0; half < 2; half++) {
            int r = r0 + half * 8;
            int b = r / NTOK, nn = r - b * NTOK;
            #pragma unroll
            for (int nt = 0; nt < 4; nt++) {
                int col = colw + nt*8 + ((lane & 3) << 1);
                float2 o;
                o.x = acc[mt][nt][2*half]   + bias[col];
                o.y = acc[mt][nt][2*half+1] + bias[col+1];
                if (qkv_mode) {
                    int d = col & 31;
                    *(float2*)(dstq + (((size_t)b * NH + h) * NTOK + nn) * HD + d) = o;
                } else {
                    *(float2*)(outp + (size_t)r * CDIM + col) = o;
                }
            }
        }
    }
}

// ---------------- CPB-MLP bias table: (529, 12) ----------------
__global__ void bias_tab_kernel(const float* __restrict__ w1,
                                const float* __restrict__ b1,
                                const float* __restrict__ w2) {
    __shared__ float hid[512];
    int t = blockIdx.x;          // 0..528
    int ti = t / 23, tj = t % 23;
    float ra = (float)(ti - 11) * (12.0f / 11.0f);
    float rb = (float)(tj - 11) * (12.0f / 11.0f);
    float sa = (ra > 0.f) ? 1.f : ((ra < 0.f) ? -1.f : 0.f);
    float sb = (rb > 0.f) ? 1.f : ((rb < 0.f) ? -1.f : 0.f);
    float t0 = sa * log2f(fabsf(ra) + 1.0f) * (1.0f / 3.0f);
    float t1 = sb * log2f(fabsf(rb) + 1.0f) * (1.0f / 3.0f);
    int j = threadIdx.x;         // 0..511
    hid[j] = fmaxf(t0 * w1[2*j] + t1 * w1[2*j+1] + b1[j], 0.0f);
    __syncthreads();
    if (j < NH) {
        float s = 0.f;
        const float* wr = w2 + j * 512;
        #pragma unroll 8
        for (int q = 0; q < 512; q++) s += hid[q] * wr[q];
        g_tab[t * NH + j] = s;
    }
}

// ---------------- gather + 16*sigmoid into (h, n, m) ----------------
__global__ void bias_gather_kernel() {
    int g = blockIdx.x * blockDim.x + threadIdx.x;
    if (g >= NH * NTOK * NTOK) return;
    int h = g / (NTOK * NTOK);
    int r = g % (NTOK * NTOK);
    int n = r / NTOK, m = r % NTOK;
    int dr = n / WSD - m / WSD + 11;
    int dc = n % WSD - m % WSD + 11;
    float v = g_tab[(dr * 23 + dc) * NH + h];
    g_bias[g] = 16.0f / (1.0f + expf(-v));
}

// ---------------- fused attention: one block per (b,h) ----------------
__global__ __launch_bounds__(256, 1) void attn_kernel(
    const float* __restrict__ mask, const float* __restrict__ logit_scale) {
    extern __shared__ float sm[];
    float* qs   = sm;                 // 144*33 = 4752
    float* ks   = qs + 4752;
    float* vs   = ks + 4752;
    float* Ssm  = vs + 4752;          // 144*145 = 20880
    float* red  = Ssm + 20880;        // 144*16 = 2304
    float* qinv = red + 2304;         // 144
    float* kinv = qinv + 144;         // 144
    float* rmax = kinv + 144;         // 144
    float* rsum = rmax + 144;         // 144

    int bh = blockIdx.x;
    int b = bh / NH, h = bh % NH;
    int w = b & 3;                    // b % NWIN
    const float* gq = g_q + (size_t)bh * NTOK * HD;
    const float* gk = g_k + (size_t)bh * NTOK * HD;
    const float* gv = g_v + (size_t)bh * NTOK * HD;
    int tid = threadIdx.x;

    for (int i = tid; i < NTOK * HD; i += 256) {
        int n = i >> 5, d = i & 31;
        qs[n*33+d] = gq[i];
        ks[n*33+d] = gk[i];
        vs[n*33+d] = gv[i];
    }
    __syncthreads();

    if (tid < NTOK) {
        float s = 0.f, t = 0.f;
        #pragma unroll
        for (int d = 0; d < 32; d++) {
            float a = qs[tid*33+d]; s += a * a;
            float c = ks[tid*33+d]; t += c * c;
        }
        qinv[tid] = 1.0f / fmaxf(sqrtf(s), 1e-12f);
        kinv[tid] = 1.0f / fmaxf(sqrtf(t), 1e-12f);
    }
    __syncthreads();

    float sc = expf(fminf(logit_scale[h], 4.6051702f));  // ln(100)

    int ty = tid >> 4, tx = tid & 15;
    float acc[9][9] = {};
    const float* qrow = qs + (ty * 9) * 33;
    const float* krow = ks + (tx * 9) * 33;
    #pragma unroll 4
    for (int kk = 0; kk < 32; kk++) {
        float a[9], c[9];
        #pragma unroll
        for (int i = 0; i < 9; i++) a[i] = qrow[i*33+kk];
        #pragma unroll
        for (int j = 0; j < 9; j++) c[j] = krow[j*33+kk];
        #pragma unroll
        for (int i = 0; i < 9; i++)
            #pragma unroll
            for (int j = 0; j < 9; j++)
                acc[i][j] += a[i] * c[j];
    }

    const float* bi = g_bias + (size_t)h * NTOK * NTOK;
    const float* mk = mask + (size_t)w * NTOK * NTOK;
    #pragma unroll
    for (int i = 0; i < 9; i++) {
        int r = ty*9 + i;
        float qv = qinv[r] * sc;
        float mx = -1e30f;
        #pragma unroll
        for (int j = 0; j < 9; j++) {
            int c = tx*9 + j;
            float v = acc[i][j] * qv * kinv[c] + bi[r*NTOK+c] + mk[r*NTOK+c];
            acc[i][j] = v;
            mx = fmaxf(mx, v);
        }
        red[r*16+tx] = mx;
    }
    __syncthreads();
    if (tid < NTOK) {
        float mx = -1e30f;
        #pragma unroll
        for (int t2 = 0; t2 < 16; t2++) mx = fmaxf(mx, red[tid*16+t2]);
        rmax[tid] = mx;
    }
    __syncthreads();

    #pragma unroll
    for (int i = 0; i < 9; i++) {
        int r = ty*9 + i;
        float mx = rmax[r];
        float s = 0.f;
        #pragma unroll
        for (int j = 0; j < 9; j++) {
            float e = __expf(acc[i][j] - mx);
            Ssm[r*145 + tx*9 + j] = e;
            s += e;
        }
        red[r*16+tx] = s;
    }
    __syncthreads();
    if (tid < NTOK) {
        float s = 0.f;
        #pragma unroll
        for (int t2 = 0; t2 < 16; t2++) s += red[tid*16+t2];
        rsum[tid] = 1.0f / s;
    }
    __syncthreads();

    // PV: out[r][d], d = tx and tx+16
    float o[9][2] = {};
    for (int m = 0; m < NTOK; m++) {
        float p[9];
        #pragma unroll
        for (int i = 0; i < 9; i++) p[i] = Ssm[(ty*9+i)*145 + m];
        float v0 = vs[m*33 + tx];
        float v1 = vs[m*33 + tx + 16];
        #pragma unroll
        for (int i = 0; i < 9; i++) {
            o[i][0] += p[i] * v0;
            o[i][1] += p[i] * v1;
        }
    }
    // write attention output as bf16 hi/lo split for the proj GEMM
    size_t obase = ((size_t)b * NTOK) * CDIM + h * HD;
    #pragma unroll
    for (int i = 0; i < 9; i++) {
        int r = ty*9 + i;
        float ri = rsum[r];
        float v0 = o[i][0] * ri;
        float v1 = o[i][1] * ri;
        __nv_bfloat16 h0, l0, h1, l1;
        split1(v0, h0, l0);
        split1(v1, h1, l1);
        size_t p0 = obase + (size_t)r * CDIM + tx;
        g_aohi[p0] = h0;      g_aolo[p0] = l0;
        g_aohi[p0 + 16] = h1; g_aolo[p0 + 16] = l1;
    }
}

// ---------------- launcher ----------------
extern "C" void kernel_launch(void* const* d_in, const int* in_sizes, int n_in,
                              void* d_out, int out_size) {
    const float* x           = (const float*)d_in[0];
    const float* mask        = (const float*)d_in[1];
    const float* qkv_w       = (const float*)d_in[2];
    const float* qkv_b       = (const float*)d_in[3];
    const float* logit_scale = (const float*)d_in[4];
    const float* cpb_w1      = (const float*)d_in[5];
    const float* cpb_b1      = (const float*)d_in[6];
    const float* cpb_w2      = (const float*)d_in[7];
    const float* proj_w      = (const float*)d_in[8];
    const float* proj_b      = (const float*)d_in[9];
    float* out = (float*)d_out;

    const int smem_attn = (4752*3 + 20880 + 2304 + 4*144) * 4;  // 152064 B
    cudaFuncSetAttribute(attn_kernel, cudaFuncAttributeMaxDynamicSharedMemorySize, smem_attn);
    cudaFuncSetAttribute(mma_gemm_kernel, cudaFuncAttributeMaxDynamicSharedMemorySize, GEMM_SMEM);

    __nv_bfloat16 *p_xhi, *p_xlo, *p_wqhi, *p_wqlo, *p_wphi, *p_wplo;
    cudaGetSymbolAddress((void**)&p_xhi, g_xhi);
    cudaGetSymbolAddress((void**)&p_xlo, g_xlo);
    cudaGetSymbolAddress((void**)&p_wqhi, g_wqhi);
    cudaGetSymbolAddress((void**)&p_wqlo, g_wqlo);
    cudaGetSymbolAddress((void**)&p_wphi, g_wphi);
    cudaGetSymbolAddress((void**)&p_wplo, g_wplo);
    __nv_bfloat16 *p_aohi, *p_aolo;
    cudaGetSymbolAddress((void**)&p_aohi, g_aohi);
    cudaGetSymbolAddress((void**)&p_aolo, g_aolo);

    conv_split_kernel<<<(MROWS*CDIM/4 + 255)/256, 256>>>(x, p_xhi, p_xlo, MROWS*CDIM/4);
    conv_split_kernel<<<(3*CDIM*CDIM/4 + 255)/256, 256>>>(qkv_w, p_wqhi, p_wqlo, 3*CDIM*CDIM/4);
    conv_split_kernel<<<(CDIM*CDIM/4 + 255)/256, 256>>>(proj_w, p_wphi, p_wplo, CDIM*CDIM/4);
    bias_tab_kernel<<<529, 512>>>(cpb_w1, cpb_b1, cpb_w2);
    bias_gather_kernel<<<(NH*NTOK*NTOK + 255)/256, 256>>>();
    // QKV: C[73728, 1152] = x @ qkv_w^T + qkv_b -> scatter q/k/v
    mma_gemm_kernel<<<dim3(9, 576), 256, GEMM_SMEM>>>(p_xhi, p_xlo, p_wqhi, p_wqlo, qkv_b, nullptr, 1);
    attn_kernel<<<BWIN*NH, 256, smem_attn>>>(mask, logit_scale);
    // proj: out[73728, 384] = attout @ proj_w^T + proj_b
    mma_gemm_kernel<<<dim3(3, 576), 256, GEMM_SMEM>>>(p_aohi, p_aolo, p_wphi, p_wplo, proj_b, out, 0);
}

// round 10
// speedup vs baseline: 1.7666x; 1.0456x over previous
#include <cuda_runtime.h>
#include <cuda_bf16.h>
#include <math.h>
#include <stdint.h>

#define WSD 12
#define NTOK 144
#define CDIM 384
#define NH 12
#define HD 32
#define NWIN 4
#define BWIN 512
#define MROWS (BWIN*NTOK)   // 73728

// ---------------- scratch (no allocations allowed) ----------------
__device__ float g_q[(size_t)BWIN*NH*NTOK*HD];
__device__ float g_k[(size_t)BWIN*NH*NTOK*HD];
__device__ float g_v[(size_t)BWIN*NH*NTOK*HD];
__device__ __nv_bfloat16 g_xhi[(size_t)MROWS*CDIM];
__device__ __nv_bfloat16 g_xlo[(size_t)MROWS*CDIM];
__device__ __nv_bfloat16 g_aohi[(size_t)MROWS*CDIM];
__device__ __nv_bfloat16 g_aolo[(size_t)MROWS*CDIM];
__device__ __nv_bfloat16 g_wqhi[3*CDIM*CDIM];
__device__ __nv_bfloat16 g_wqlo[3*CDIM*CDIM];
__device__ __nv_bfloat16 g_wphi[CDIM*CDIM];
__device__ __nv_bfloat16 g_wplo[CDIM*CDIM];
__device__ float g_tab[529*NH];
__device__ float g_bias[NH*NTOK*NTOK];

// ================= helpers =================
__device__ __forceinline__ uint32_t smem_u32(const void* p) {
    uint32_t a;
    asm("{ .reg .u64 t; cvta.to.shared.u64 t, %1; cvt.u32.u64 %0, t; }" : "=r"(a) : "l"(p));
    return a;
}
__device__ __forceinline__ void ldsm4(uint32_t* r, uint32_t addr) {
    asm volatile("ldmatrix.sync.aligned.m8n8.x4.shared.b16 {%0,%1,%2,%3}, [%4];"
        : "=r"(r[0]), "=r"(r[1]), "=r"(r[2]), "=r"(r[3]) : "r"(addr));
}
__device__ __forceinline__ void mma16816(float* c, const uint32_t* a, const uint32_t* b) {
    asm volatile("mma.sync.aligned.m16n8k16.row.col.f32.bf16.bf16.f32 "
        "{%0,%1,%2,%3}, {%4,%5,%6,%7}, {%8,%9}, {%0,%1,%2,%3};"
        : "+f"(c[0]), "+f"(c[1]), "+f"(c[2]), "+f"(c[3])
        : "r"(a[0]), "r"(a[1]), "r"(a[2]), "r"(a[3]), "r"(b[0]), "r"(b[1]));
}
__device__ __forceinline__ void split1(float v, __nv_bfloat16& h, __nv_bfloat16& l) {
    h = __float2bfloat16(v);
    l = __float2bfloat16(v - __bfloat162float(h));
}
#define CP_ASYNC16(dst, src) \
    asm volatile("cp.async.cg.shared.global [%0], [%1], 16;" :: "r"(dst), "l"(src) : "memory")
#define CP_COMMIT() asm volatile("cp.async.commit_group;" ::: "memory")
#define CP_WAIT1() asm volatile("cp.async.wait_group 1;" ::: "memory")
#define CP_WAIT0() asm volatile("cp.async.wait_group 0;" ::: "memory")

// ---------------- fp32 -> bf16 hi/lo split ----------------
__global__ void conv_split_kernel(const float* __restrict__ src,
                                  __nv_bfloat16* __restrict__ hi,
                                  __nv_bfloat16* __restrict__ lo, int n4) {
    int i = blockIdx.x * blockDim.x + threadIdx.x;
    if (i >= n4) return;
    float4 v = ((const float4*)src)[i];
    __nv_bfloat16 h0, l0, h1, l1, h2, l2, h3, l3;
    split1(v.x, h0, l0); split1(v.y, h1, l1);
    split1(v.z, h2, l2); split1(v.w, h3, l3);
    uint2 ph, pl;
    ph.x = (uint32_t)__bfloat16_as_ushort(h0) | ((uint32_t)__bfloat16_as_ushort(h1) << 16);
    ph.y = (uint32_t)__bfloat16_as_ushort(h2) | ((uint32_t)__bfloat16_as_ushort(h3) << 16);
    pl.x = (uint32_t)__bfloat16_as_ushort(l0) | ((uint32_t)__bfloat16_as_ushort(l1) << 16);
    pl.y = (uint32_t)__bfloat16_as_ushort(l2) | ((uint32_t)__bfloat16_as_ushort(l3) << 16);
    *(uint2*)(hi + 4*(size_t)i) = ph;
    *(uint2*)(lo + 4*(size_t)i) = pl;
}

// ================= mma.sync GEMM (cp.async double-buffered) =================
// C[M,Ntot] = A[M,384] @ W[Ntot,384]^T + bias.  CTA tile 128x128, warp tile 64x32.
// 3-product bf16 split into shared fp32 accumulators.
#define LDSB 144            // smem row stride bytes (72 bf16)
#define A_HI 0
#define A_LO 18432
#define B_HI 36864
#define B_LO 55296
#define STAGE 73728
#define GEMM_SMEM (2*STAGE)

__global__ __launch_bounds__(256, 1)
void mma_gemm_kernel(const __nv_bfloat16* __restrict__ Ahi,
                     const __nv_bfloat16* __restrict__ Alo,
                     const __nv_bfloat16* __restrict__ Bhi,
                     const __nv_bfloat16* __restrict__ Blo,
                     const float* __restrict__ bias,
                     float* __restrict__ outp,
                     int qkv_mode)
{
    extern __shared__ char smem[];
    uint32_t sb = smem_u32(smem);
    int tid = threadIdx.x;
    int wid = tid >> 5, lane = tid & 31;
    int wm = wid & 1, wn = wid >> 1;
    int m0 = blockIdx.y * 128, n0 = blockIdx.x * 128;

    float acc[4][4][4] = {};

    // per-lane ldmatrix address components
    uint32_t aoff = (uint32_t)((wm*64 + (lane & 15)) * LDSB + (((lane >> 4) & 1) << 4));
    uint32_t boff = (uint32_t)((wn*32 + (lane & 7) + ((lane & 16) >> 1)) * LDSB + ((lane & 8) << 1));

    // per-thread fill coordinates: 4 rows of 8 bf16 per matrix per chunk
    int frow = tid >> 3, fc8 = (tid & 7) << 3;
    uint32_t fso = (uint32_t)(frow * LDSB + (fc8 << 1));

    // prefetch chunk 0 into stage 0
    {
        size_t gaB = (size_t)(m0 + frow) * CDIM + fc8;
        size_t gbB = (size_t)(n0 + frow) * CDIM + fc8;
        #pragma unroll
        for (int i = 0; i < 4; i++) {
            uint32_t so = fso + (uint32_t)(i * 32 * LDSB);
            size_t ga = gaB + (size_t)i * 32 * CDIM;
            size_t gb = gbB + (size_t)i * 32 * CDIM;
            CP_ASYNC16(sb + A_HI + so, Ahi + ga);
            CP_ASYNC16(sb + A_LO + so, Alo + ga);
            CP_ASYNC16(sb + B_HI + so, Bhi + gb);
            CP_ASYNC16(sb + B_LO + so, Blo + gb);
        }
        CP_COMMIT();
    }

    for (int c = 0; c < 6; c++) {
        uint32_t cur = sb + (uint32_t)((c & 1) * STAGE);
        if (c < 5) {
            uint32_t nxt = sb + (uint32_t)(((c + 1) & 1) * STAGE);
            int kc = (c + 1) * 64;
            size_t gaB = (size_t)(m0 + frow) * CDIM + kc + fc8;
            size_t gbB = (size_t)(n0 + frow) * CDIM + kc + fc8;
            #pragma unroll
            for (int i = 0; i < 4; i++) {
                uint32_t so = fso + (uint32_t)(i * 32 * LDSB);
                size_t ga = gaB + (size_t)i * 32 * CDIM;
                size_t gb = gbB + (size_t)i * 32 * CDIM;
                CP_ASYNC16(nxt + A_HI + so, Ahi + ga);
                CP_ASYNC16(nxt + A_LO + so, Alo + ga);
                CP_ASYNC16(nxt + B_HI + so, Bhi + gb);
                CP_ASYNC16(nxt + B_LO + so, Blo + gb);
            }
            CP_COMMIT();
            CP_WAIT1();
        } else {
            CP_WAIT0();
        }
        __syncthreads();

        #pragma unroll
        for (int ks = 0; ks < 4; ks++) {
            uint32_t ahi[4][4], alo[4][4], bhi[2][4], blo[2][4];
            uint32_t kb = (uint32_t)(ks << 5);
            #pragma unroll
            for (int mt = 0; mt < 4; mt++) {
                ldsm4(ahi[mt], cur + A_HI + aoff + mt*(16*LDSB) + kb);
                ldsm4(alo[mt], cur + A_LO + aoff + mt*(16*LDSB) + kb);
            }
            #pragma unroll
            for (int tp = 0; tp < 2; tp++) {
                ldsm4(bhi[tp], cur + B_HI + boff + tp*(16*LDSB) + kb);
                ldsm4(blo[tp], cur + B_LO + boff + tp*(16*LDSB) + kb);
            }
            #pragma unroll
            for (int mt = 0; mt < 4; mt++) {
                #pragma unroll
                for (int tp = 0; tp < 2; tp++) {
                    mma16816(acc[mt][2*tp],   ahi[mt], &bhi[tp][0]);
                    mma16816(acc[mt][2*tp+1], ahi[mt], &bhi[tp][2]);
                    mma16816(acc[mt][2*tp],   ahi[mt], &blo[tp][0]);
                    mma16816(acc[mt][2*tp+1], ahi[mt], &blo[tp][2]);
                    mma16816(acc[mt][2*tp],   alo[mt], &bhi[tp][0]);
                    mma16816(acc[mt][2*tp+1], alo[mt], &bhi[tp][2]);
                }
            }
        }
        __syncthreads();
    }

    // epilogue
    int colw = n0 + wn * 32;
    float* dstq = nullptr;
    int which = 0, h = 0;
    if (qkv_mode) {
        which = colw / CDIM;
        int rem = colw - which * CDIM;
        h = rem >> 5;
        dstq = (which == 0) ? g_q : ((which == 1) ? g_k : g_v);
    }
    #pragma unroll
    for (int mt = 0; mt < 4; mt++) {
        int r0 = m0 + wm*64 + mt*16 + (lane >> 2);
        #pragma unroll
        for (int half = 0; half < 2; half++) {
            int r = r0 + half * 8;
            int b = r / NTOK, nn = r - b * NTOK;
            #pragma unroll
            for (int nt = 0; nt < 4; nt++) {
                int col = colw + nt*8 + ((lane & 3) << 1);
                float2 o;
                o.x = acc[mt][nt][2*half]   + bias[col];
                o.y = acc[mt][nt][2*half+1] + bias[col+1];
                if (qkv_mode) {
                    int d = col & 31;
                    *(float2*)(dstq + (((size_t)b * NH + h) * NTOK + nn) * HD + d) = o;
                } else {
                    *(float2*)(outp + (size_t)r * CDIM + col) = o;
                }
            }
        }
    }
}

// ---------------- CPB-MLP bias table: (529, 12) ----------------
__global__ void bias_tab_kernel(const float* __restrict__ w1,
                                const float* __restrict__ b1,
                                const float* __restrict__ w2) {
    __shared__ float hid[512];
    int t = blockIdx.x;          // 0..528
    int ti = t / 23, tj = t % 23;
    float ra = (float)(ti - 11) * (12.0f / 11.0f);
    float rb = (float)(tj - 11) * (12.0f / 11.0f);
    float sa = (ra > 0.f) ? 1.f : ((ra < 0.f) ? -1.f : 0.f);
    float sb = (rb > 0.f) ? 1.f : ((rb < 0.f) ? -1.f : 0.f);
    float t0 = sa * log2f(fabsf(ra) + 1.0f) * (1.0f / 3.0f);
    float t1 = sb * log2f(fabsf(rb) + 1.0f) * (1.0f / 3.0f);
    int j = threadIdx.x;         // 0..511
    hid[j] = fmaxf(t0 * w1[2*j] + t1 * w1[2*j+1] + b1[j], 0.0f);
    __syncthreads();
    int wid = j >> 5, lane = j & 31;
    if (wid < NH) {
        const float* wr = w2 + wid * 512;
        float s = 0.f;
        #pragma unroll
        for (int q = 0; q < 16; q++) s += hid[lane + 32*q] * wr[lane + 32*q];
        #pragma unroll
        for (int o = 16; o; o >>= 1) s += __shfl_xor_sync(0xFFFFFFFFu, s, o);
        if (lane == 0) g_tab[t * NH + wid] = s;
    }
}

// ---------------- gather + 16*sigmoid into (h, n, m) ----------------
__global__ void bias_gather_kernel() {
    int g = blockIdx.x * blockDim.x + threadIdx.x;
    if (g >= NH * NTOK * NTOK) return;
    int h = g / (NTOK * NTOK);
    int r = g % (NTOK * NTOK);
    int n = r / NTOK, m = r % NTOK;
    int dr = n / WSD - m / WSD + 11;
    int dc = n % WSD - m % WSD + 11;
    float v = g_tab[(dr * 23 + dc) * NH + h];
    g_bias[g] = 16.0f / (1.0f + expf(-v));
}

// ---------------- fused attention: one block per (b,h) ----------------
__global__ __launch_bounds__(256, 1) void attn_kernel(
    const float* __restrict__ mask, const float* __restrict__ logit_scale) {
    extern __shared__ float sm[];
    float* qs   = sm;                 // 144*33 = 4752
    float* ks   = qs + 4752;
    float* vs   = ks + 4752;
    float* Ssm  = vs + 4752;          // 144*145 = 20880
    float* red  = Ssm + 20880;        // 144*16 = 2304
    float* qinv = red + 2304;         // 144
    float* kinv = qinv + 144;         // 144
    float* rmax = kinv + 144;         // 144
    float* rsum = rmax + 144;         // 144

    int bh = blockIdx.x;
    int b = bh / NH, h = bh % NH;
    int w = b & 3;                    // b % NWIN
    const float* gq = g_q + (size_t)bh * NTOK * HD;
    const float* gk = g_k + (size_t)bh * NTOK * HD;
    const float* gv = g_v + (size_t)bh * NTOK * HD;
    int tid = threadIdx.x;

    for (int i = tid; i < NTOK * HD; i += 256) {
        int n = i >> 5, d = i & 31;
        qs[n*33+d] = gq[i];
        ks[n*33+d] = gk[i];
        vs[n*33+d] = gv[i];
    }
    __syncthreads();

    if (tid < NTOK) {
        float s = 0.f, t = 0.f;
        #pragma unroll
        for (int d = 0; d < 32; d++) {
            float a = qs[tid*33+d]; s += a * a;
            float c = ks[tid*33+d]; t += c * c;
        }
        qinv[tid] = 1.0f / fmaxf(sqrtf(s), 1e-12f);
        kinv[tid] = 1.0f / fmaxf(sqrtf(t), 1e-12f);
    }
    __syncthreads();

    float sc = expf(fminf(logit_scale[h], 4.6051702f));  // ln(100)

    int ty = tid >> 4, tx = tid & 15;
    float acc[9][9] = {};
    const float* qrow = qs + (ty * 9) * 33;
    const float* krow = ks + (tx * 9) * 33;
    #pragma unroll 4
    for (int kk = 0; kk < 32; kk++) {
        float a[9], c[9];
        #pragma unroll
        for (int i = 0; i < 9; i++) a[i] = qrow[i*33+kk];
        #pragma unroll
        for (int j = 0; j < 9; j++) c[j] = krow[j*33+kk];
        #pragma unroll
        for (int i = 0; i < 9; i++)
            #pragma unroll
            for (int j = 0; j < 9; j++)
                acc[i][j] += a[i] * c[j];
    }

    const float* bi = g_bias + (size_t)h * NTOK * NTOK;
    const float* mk = mask + (size_t)w * NTOK * NTOK;
    #pragma unroll
    for (int i = 0; i < 9; i++) {
        int r = ty*9 + i;
        float qv = qinv[r] * sc;
        float mx = -1e30f;
        #pragma unroll
        for (int j = 0; j < 9; j++) {
            int c = tx*9 + j;
            float v = acc[i][j] * qv * kinv[c] + bi[r*NTOK+c] + mk[r*NTOK+c];
            acc[i][j] = v;
            mx = fmaxf(mx, v);
        }
        red[r*16+tx] = mx;
    }
    __syncthreads();
    if (tid < NTOK) {
        float mx = -1e30f;
        #pragma unroll
        for (int t2 = 0; t2 < 16; t2++) mx = fmaxf(mx, red[tid*16+t2]);
        rmax[tid] = mx;
    }
    __syncthreads();

    #pragma unroll
    for (int i = 0; i < 9; i++) {
        int r = ty*9 + i;
        float mx = rmax[r];
        float s = 0.f;
        #pragma unroll
        for (int j = 0; j < 9; j++) {
            float e = __expf(acc[i][j] - mx);
            Ssm[r*145 + tx*9 + j] = e;
            s += e;
        }
        red[r*16+tx] = s;
    }
    __syncthreads();
    if (tid < NTOK) {
        float s = 0.f;
        #pragma unroll
        for (int t2 = 0; t2 < 16; t2++) s += red[tid*16+t2];
        rsum[tid] = 1.0f / s;
    }
    __syncthreads();

    // PV: out[r][d], d = tx and tx+16
    float o[9][2] = {};
    for (int m = 0; m < NTOK; m++) {
        float p[9];
        #pragma unroll
        for (int i = 0; i < 9; i++) p[i] = Ssm[(ty*9+i)*145 + m];
        float v0 = vs[m*33 + tx];
        float v1 = vs[m*33 + tx + 16];
        #pragma unroll
        for (int i = 0; i < 9; i++) {
            o[i][0] += p[i] * v0;
            o[i][1] += p[i] * v1;
        }
    }
    // write attention output as bf16 hi/lo split for the proj GEMM
    size_t obase = ((size_t)b * NTOK) * CDIM + h * HD;
    #pragma unroll
    for (int i = 0; i < 9; i++) {
        int r = ty*9 + i;
        float ri = rsum[r];
        float v0 = o[i][0] * ri;
        float v1 = o[i][1] * ri;
        __nv_bfloat16 h0, l0, h1, l1;
        split1(v0, h0, l0);
        split1(v1, h1, l1);
        size_t p0 = obase + (size_t)r * CDIM + tx;
        g_aohi[p0] = h0;      g_aolo[p0] = l0;
        g_aohi[p0 + 16] = h1; g_aolo[p0 + 16] = l1;
    }
}

// ---------------- launcher ----------------
extern "C" void kernel_launch(void* const* d_in, const int* in_sizes, int n_in,
                              void* d_out, int out_size) {
    const float* x           = (const float*)d_in[0];
    const float* mask        = (const float*)d_in[1];
    const float* qkv_w       = (const float*)d_in[2];
    const float* qkv_b       = (const float*)d_in[3];
    const float* logit_scale = (const float*)d_in[4];
    const float* cpb_w1      = (const float*)d_in[5];
    const float* cpb_b1      = (const float*)d_in[6];
    const float* cpb_w2      = (const float*)d_in[7];
    const float* proj_w      = (const float*)d_in[8];
    const float* proj_b      = (const float*)d_in[9];
    float* out = (float*)d_out;

    const int smem_attn = (4752*3 + 20880 + 2304 + 4*144) * 4;  // 152064 B
    cudaFuncSetAttribute(attn_kernel, cudaFuncAttributeMaxDynamicSharedMemorySize, smem_attn);
    cudaFuncSetAttribute(mma_gemm_kernel, cudaFuncAttributeMaxDynamicSharedMemorySize, GEMM_SMEM);

    __nv_bfloat16 *p_xhi, *p_xlo, *p_wqhi, *p_wqlo, *p_wphi, *p_wplo;
    cudaGetSymbolAddress((void**)&p_xhi, g_xhi);
    cudaGetSymbolAddress((void**)&p_xlo, g_xlo);
    cudaGetSymbolAddress((void**)&p_wqhi, g_wqhi);
    cudaGetSymbolAddress((void**)&p_wqlo, g_wqlo);
    cudaGetSymbolAddress((void**)&p_wphi, g_wphi);
    cudaGetSymbolAddress((void**)&p_wplo, g_wplo);
    __nv_bfloat16 *p_aohi, *p_aolo;
    cudaGetSymbolAddress((void**)&p_aohi, g_aohi);
    cudaGetSymbolAddress((void**)&p_aolo, g_aolo);

    conv_split_kernel<<<(MROWS*CDIM/4 + 255)/256, 256>>>(x, p_xhi, p_xlo, MROWS*CDIM/4);
    conv_split_kernel<<<(3*CDIM*CDIM/4 + 255)/256, 256>>>(qkv_w, p_wqhi, p_wqlo, 3*CDIM*CDIM/4);
    conv_split_kernel<<<(CDIM*CDIM/4 + 255)/256, 256>>>(proj_w, p_wphi, p_wplo, CDIM*CDIM/4);
    bias_tab_kernel<<<529, 512>>>(cpb_w1, cpb_b1, cpb_w2);
    bias_gather_kernel<<<(NH*NTOK*NTOK + 255)/256, 256>>>();
    // QKV: C[73728, 1152] = x @ qkv_w^T + qkv_b -> scatter q/k/v
    mma_gemm_kernel<<<dim3(9, 576), 256, GEMM_SMEM>>>(p_xhi, p_xlo, p_wqhi, p_wqlo, qkv_b, nullptr, 1);
    attn_kernel<<<BWIN*NH, 256, smem_attn>>>(mask, logit_scale);
    // proj: out[73728, 384] = attout @ proj_w^T + proj_b
    mma_gemm_kernel<<<dim3(3, 576), 256, GEMM_SMEM>>>(p_aohi, p_aolo, p_wphi, p_wplo, proj_b, out, 0);
}

// round 12
// speedup vs baseline: 2.2320x; 1.2635x over previous
#include <cuda_runtime.h>
#include <cuda_bf16.h>
#include <math.h>
#include <stdint.h>

#define WSD 12
#define NTOK 144
#define CDIM 384
#define NH 12
#define HD 32
#define NWIN 4
#define BWIN 512
#define MROWS (BWIN*NTOK)   // 73728

// ---------------- scratch (no allocations allowed) ----------------
__device__ float g_q[(size_t)BWIN*NH*NTOK*HD];
__device__ float g_k[(size_t)BWIN*NH*NTOK*HD];
__device__ float g_v[(size_t)BWIN*NH*NTOK*HD];
__device__ __nv_bfloat16 g_xhi[(size_t)MROWS*CDIM];
__device__ __nv_bfloat16 g_xlo[(size_t)MROWS*CDIM];
__device__ __nv_bfloat16 g_aohi[(size_t)MROWS*CDIM];
__device__ __nv_bfloat16 g_aolo[(size_t)MROWS*CDIM];
__device__ __nv_bfloat16 g_wqhi[3*CDIM*CDIM];
__device__ __nv_bfloat16 g_wqlo[3*CDIM*CDIM];
__device__ __nv_bfloat16 g_wphi[CDIM*CDIM];
__device__ __nv_bfloat16 g_wplo[CDIM*CDIM];
__device__ float g_tab[529*NH];
__device__ float g_bias[NH*NTOK*NTOK];

// ================= helpers =================
__device__ __forceinline__ uint32_t smem_u32(const void* p) {
    uint32_t a;
    asm("{ .reg .u64 t; cvta.to.shared.u64 t, %1; cvt.u32.u64 %0, t; }" : "=r"(a) : "l"(p));
    return a;
}
__device__ __forceinline__ void ldsm4(uint32_t* r, uint32_t addr) {
    asm volatile("ldmatrix.sync.aligned.m8n8.x4.shared.b16 {%0,%1,%2,%3}, [%4];"
        : "=r"(r[0]), "=r"(r[1]), "=r"(r[2]), "=r"(r[3]) : "r"(addr));
}
__device__ __forceinline__ void ldsm4t(uint32_t* r, uint32_t addr) {
    asm volatile("ldmatrix.sync.aligned.m8n8.x4.trans.shared.b16 {%0,%1,%2,%3}, [%4];"
        : "=r"(r[0]), "=r"(r[1]), "=r"(r[2]), "=r"(r[3]) : "r"(addr));
}
__device__ __forceinline__ void mma16816(float* c, const uint32_t* a, const uint32_t* b) {
    asm volatile("mma.sync.aligned.m16n8k16.row.col.f32.bf16.bf16.f32 "
        "{%0,%1,%2,%3}, {%4,%5,%6,%7}, {%8,%9}, {%0,%1,%2,%3};"
        : "+f"(c[0]), "+f"(c[1]), "+f"(c[2]), "+f"(c[3])
        : "r"(a[0]), "r"(a[1]), "r"(a[2]), "r"(a[3]), "r"(b[0]), "r"(b[1]));
}
__device__ __forceinline__ void split1(float v, __nv_bfloat16& h, __nv_bfloat16& l) {
    h = __float2bfloat16(v);
    l = __float2bfloat16(v - __bfloat162float(h));
}
__device__ __forceinline__ uint32_t pack2(__nv_bfloat16 a, __nv_bfloat16 b) {
    return (uint32_t)__bfloat16_as_ushort(a) | ((uint32_t)__bfloat16_as_ushort(b) << 16);
}
#define CP_ASYNC16(dst, src) \
    asm volatile("cp.async.cg.shared.global [%0], [%1], 16;" :: "r"(dst), "l"(src) : "memory")
#define CP_COMMIT() asm volatile("cp.async.commit_group;" ::: "memory")
#define CP_WAIT1() asm volatile("cp.async.wait_group 1;" ::: "memory")
#define CP_WAIT0() asm volatile("cp.async.wait_group 0;" ::: "memory")

// ---------------- fp32 -> bf16 hi/lo split ----------------
__global__ void conv_split_kernel(const float* __restrict__ src,
                                  __nv_bfloat16* __restrict__ hi,
                                  __nv_bfloat16* __restrict__ lo, int n4) {
    int i = blockIdx.x * blockDim.x + threadIdx.x;
    if (i >= n4) return;
    float4 v = ((const float4*)src)[i];
    __nv_bfloat16 h0, l0, h1, l1, h2, l2, h3, l3;
    split1(v.x, h0, l0); split1(v.y, h1, l1);
    split1(v.z, h2, l2); split1(v.w, h3, l3);
    uint2 ph, pl;
    ph.x = pack2(h0, h1); ph.y = pack2(h2, h3);
    pl.x = pack2(l0, l1); pl.y = pack2(l2, l3);
    *(uint2*)(hi + 4*(size_t)i) = ph;
    *(uint2*)(lo + 4*(size_t)i) = pl;
}

// ================= mma.sync GEMM (cp.async double-buffered) =================
#define LDSB 144
#define A_HI 0
#define A_LO 18432
#define B_HI 36864
#define B_LO 55296
#define STAGE 73728
#define GEMM_SMEM (2*STAGE)

__global__ __launch_bounds__(256, 1)
void mma_gemm_kernel(const __nv_bfloat16* __restrict__ Ahi,
                     const __nv_bfloat16* __restrict__ Alo,
                     const __nv_bfloat16* __restrict__ Bhi,
                     const __nv_bfloat16* __restrict__ Blo,
                     const float* __restrict__ bias,
                     float* __restrict__ outp,
                     int qkv_mode)
{
    extern __shared__ char smem[];
    uint32_t sb = smem_u32(smem);
    int tid = threadIdx.x;
    int wid = tid >> 5, lane = tid & 31;
    int wm = wid & 1, wn = wid >> 1;
    int m0 = blockIdx.y * 128, n0 = blockIdx.x * 128;

    float acc[4][4][4] = {};

    uint32_t aoff = (uint32_t)((wm*64 + (lane & 15)) * LDSB + (((lane >> 4) & 1) << 4));
    uint32_t boff = (uint32_t)((wn*32 + (lane & 7) + ((lane & 16) >> 1)) * LDSB + ((lane & 8) << 1));

    int frow = tid >> 3, fc8 = (tid & 7) << 3;
    uint32_t fso = (uint32_t)(frow * LDSB + (fc8 << 1));

    {
        size_t gaB = (size_t)(m0 + frow) * CDIM + fc8;
        size_t gbB = (size_t)(n0 + frow) * CDIM + fc8;
        #pragma unroll
        for (int i = 0; i < 4; i++) {
            uint32_t so = fso + (uint32_t)(i * 32 * LDSB);
            size_t ga = gaB + (size_t)i * 32 * CDIM;
            size_t gb = gbB + (size_t)i * 32 * CDIM;
            CP_ASYNC16(sb + A_HI + so, Ahi + ga);
            CP_ASYNC16(sb + A_LO + so, Alo + ga);
            CP_ASYNC16(sb + B_HI + so, Bhi + gb);
            CP_ASYNC16(sb + B_LO + so, Blo + gb);
        }
        CP_COMMIT();
    }

    for (int c = 0; c < 6; c++) {
        uint32_t cur = sb + (uint32_t)((c & 1) * STAGE);
        if (c < 5) {
            uint32_t nxt = sb + (uint32_t)(((c + 1) & 1) * STAGE);
            int kc = (c + 1) * 64;
            size_t gaB = (size_t)(m0 + frow) * CDIM + kc + fc8;
            size_t gbB = (size_t)(n0 + frow) * CDIM + kc + fc8;
            #pragma unroll
            for (int i = 0; i < 4; i++) {
                uint32_t so = fso + (uint32_t)(i * 32 * LDSB);
                size_t ga = gaB + (size_t)i * 32 * CDIM;
                size_t gb = gbB + (size_t)i * 32 * CDIM;
                CP_ASYNC16(nxt + A_HI + so, Ahi + ga);
                CP_ASYNC16(nxt + A_LO + so, Alo + ga);
                CP_ASYNC16(nxt + B_HI + so, Bhi + gb);
                CP_ASYNC16(nxt + B_LO + so, Blo + gb);
            }
            CP_COMMIT();
            CP_WAIT1();
        } else {
            CP_WAIT0();
        }
        __syncthreads();

        #pragma unroll
        for (int ks = 0; ks < 4; ks++) {
            uint32_t ahi[4][4], alo[4][4], bhi[2][4], blo[2][4];
            uint32_t kb = (uint32_t)(ks << 5);
            #pragma unroll
            for (int mt = 0; mt < 4; mt++) {
                ldsm4(ahi[mt], cur + A_HI + aoff + mt*(16*LDSB) + kb);
                ldsm4(alo[mt], cur + A_LO + aoff + mt*(16*LDSB) + kb);
            }
            #pragma unroll
            for (int tp = 0; tp < 2; tp++) {
                ldsm4(bhi[tp], cur + B_HI + boff + tp*(16*LDSB) + kb);
                ldsm4(blo[tp], cur + B_LO + boff + tp*(16*LDSB) + kb);
            }
            #pragma unroll
            for (int mt = 0; mt < 4; mt++) {
                #pragma unroll
                for (int tp = 0; tp < 2; tp++) {
                    mma16816(acc[mt][2*tp],   ahi[mt], &bhi[tp][0]);
                    mma16816(acc[mt][2*tp+1], ahi[mt], &bhi[tp][2]);
                    mma16816(acc[mt][2*tp],   ahi[mt], &blo[tp][0]);
                    mma16816(acc[mt][2*tp+1], ahi[mt], &blo[tp][2]);
                    mma16816(acc[mt][2*tp],   alo[mt], &bhi[tp][0]);
                    mma16816(acc[mt][2*tp+1], alo[mt], &bhi[tp][2]);
                }
            }
        }
        __syncthreads();
    }

    int colw = n0 + wn * 32;
    float* dstq = nullptr;
    int which = 0, h = 0;
    if (qkv_mode) {
        which = colw / CDIM;
        int rem = colw - which * CDIM;
        h = rem >> 5;
        dstq = (which == 0) ? g_q : ((which == 1) ? g_k : g_v);
    }
    #pragma unroll
    for (int mt = 0; mt < 4; mt++) {
        int r0 = m0 + wm*64 + mt*16 + (lane >> 2);
        #pragma unroll
        for (int half = 0; half < 2; half++) {
            int r = r0 + half * 8;
            int b = r / NTOK, nn = r - b * NTOK;
            #pragma unroll
            for (int nt = 0; nt < 4; nt++) {
                int col = colw + nt*8 + ((lane & 3) << 1);
                float2 o;
                o.x = acc[mt][nt][2*half]   + bias[col];
                o.y = acc[mt][nt][2*half+1] + bias[col+1];
                if (qkv_mode) {
                    int d = col & 31;
                    *(float2*)(dstq + (((size_t)b * NH + h) * NTOK + nn) * HD + d) = o;
                } else {
                    *(float2*)(outp + (size_t)r * CDIM + col) = o;
                }
            }
        }
    }
}

// ---------------- CPB-MLP bias table: (529, 12) ----------------
__global__ void bias_tab_kernel(const float* __restrict__ w1,
                                const float* __restrict__ b1,
                                const float* __restrict__ w2) {
    __shared__ float hid[512];
    int t = blockIdx.x;
    int ti = t / 23, tj = t % 23;
    float ra = (float)(ti - 11) * (12.0f / 11.0f);
    float rb = (float)(tj - 11) * (12.0f / 11.0f);
    float sa = (ra > 0.f) ? 1.f : ((ra < 0.f) ? -1.f : 0.f);
    float sb = (rb > 0.f) ? 1.f : ((rb < 0.f) ? -1.f : 0.f);
    float t0 = sa * log2f(fabsf(ra) + 1.0f) * (1.0f / 3.0f);
    float t1 = sb * log2f(fabsf(rb) + 1.0f) * (1.0f / 3.0f);
    int j = threadIdx.x;
    hid[j] = fmaxf(t0 * w1[2*j] + t1 * w1[2*j+1] + b1[j], 0.0f);
    __syncthreads();
    int wid = j >> 5, lane = j & 31;
    if (wid < NH) {
        const float* wr = w2 + wid * 512;
        float s = 0.f;
        #pragma unroll
        for (int q = 0; q < 16; q++) s += hid[lane + 32*q] * wr[lane + 32*q];
        #pragma unroll
        for (int o = 16; o; o >>= 1) s += __shfl_xor_sync(0xFFFFFFFFu, s, o);
        if (lane == 0) g_tab[t * NH + wid] = s;
    }
}

// ---------------- gather + 16*sigmoid into (h, n, m) ----------------
__global__ void bias_gather_kernel() {
    int g = blockIdx.x * blockDim.x + threadIdx.x;
    if (g >= NH * NTOK * NTOK) return;
    int h = g / (NTOK * NTOK);
    int r = g % (NTOK * NTOK);
    int n = r / NTOK, m = r % NTOK;
    int dr = n / WSD - m / WSD + 11;
    int dc = n % WSD - m % WSD + 11;
    float v = g_tab[(dr * 23 + dc) * NH + h];
    g_bias[g] = 16.0f / (1.0f + expf(-v));
}

// ================= tensor-core attention: one CTA per (b,h) =================
// Smem layout (bytes):
//   [0, 85248)            Ssm: 144 x 148 f32 logits
//   [85248, 172800)       region R: q/k hi-lo tiles (80B stride) then P hi/lo tiles (304B stride, aliases q/k)
//   [172800, 195840)      V hi/lo tiles (80B stride)
//   [195840, 196416)      rsum inverse (144 f32)
#define SST 148
#define OFF_R 85248
#define QHI_O 0
#define QLO_O 11520
#define KHI_O 23040
#define KLO_O 34560
#define PSTR 304
#define PHI_O 0
#define PLO_O 43776
#define OFF_V 172800
#define VHI_O 0
#define VLO_O 11520
#define OFF_SUM 195840
#define ATTN_SMEM 196416

__global__ __launch_bounds__(256, 1) void attn_mma_kernel(
    const float* __restrict__ mask, const float* __restrict__ logit_scale) {
    extern __shared__ char smc[];
    float* Ssm  = (float*)smc;
    float* rsum = (float*)(smc + OFF_SUM);
    uint32_t sb = smem_u32(smc);

    int bh = blockIdx.x;
    int b = bh / NH, h = bh - b * NH;
    int w = b & 3;
    const float* gq = g_q + (size_t)bh * NTOK * HD;
    const float* gk = g_k + (size_t)bh * NTOK * HD;
    const float* gv = g_v + (size_t)bh * NTOK * HD;
    int tid = threadIdx.x, wid = tid >> 5, lane = tid & 31;

    float sc = expf(fminf(logit_scale[h], 4.6051702f));  // ln(100)

    // ---- load q,k,v; prescale q,k; split to bf16 hi/lo tiles ----
    if (tid < NTOK) {
        {
            const float4* p4 = (const float4*)(gq + tid * HD);
            float4 t[8]; float s = 0.f;
            #pragma unroll
            for (int i = 0; i < 8; i++) {
                t[i] = p4[i];
                s += t[i].x*t[i].x + t[i].y*t[i].y + t[i].z*t[i].z + t[i].w*t[i].w;
            }
            float qi = sc / fmaxf(sqrtf(s), 1e-12f);
            uint32_t* dh = (uint32_t*)(smc + OFF_R + QHI_O + tid * 80);
            uint32_t* dl = (uint32_t*)(smc + OFF_R + QLO_O + tid * 80);
            #pragma unroll
            for (int i = 0; i < 8; i++) {
                __nv_bfloat16 h0,l0,h1,l1,h2,l2,h3,l3;
                split1(t[i].x*qi, h0, l0); split1(t[i].y*qi, h1, l1);
                split1(t[i].z*qi, h2, l2); split1(t[i].w*qi, h3, l3);
                dh[2*i]   = pack2(h0, h1); dh[2*i+1] = pack2(h2, h3);
                dl[2*i]   = pack2(l0, l1); dl[2*i+1] = pack2(l2, l3);
            }
        }
        {
            const float4* p4 = (const float4*)(gk + tid * HD);
            float4 t[8]; float s = 0.f;
            #pragma unroll
            for (int i = 0; i < 8; i++) {
                t[i] = p4[i];
                s += t[i].x*t[i].x + t[i].y*t[i].y + t[i].z*t[i].z + t[i].w*t[i].w;
            }
            float ki = 1.0f / fmaxf(sqrtf(s), 1e-12f);
            uint32_t* dh = (uint32_t*)(smc + OFF_R + KHI_O + tid * 80);
            uint32_t* dl = (uint32_t*)(smc + OFF_R + KLO_O + tid * 80);
            #pragma unroll
            for (int i = 0; i < 8; i++) {
                __nv_bfloat16 h0,l0,h1,l1,h2,l2,h3,l3;
                split1(t[i].x*ki, h0, l0); split1(t[i].y*ki, h1, l1);
                split1(t[i].z*ki, h2, l2); split1(t[i].w*ki, h3, l3);
                dh[2*i]   = pack2(h0, h1); dh[2*i+1] = pack2(h2, h3);
                dl[2*i]   = pack2(l0, l1); dl[2*i+1] = pack2(l2, l3);
            }
        }
        {
            const float4* p4 = (const float4*)(gv + tid * HD);
            uint32_t* dh = (uint32_t*)(smc + OFF_V + VHI_O + tid * 80);
            uint32_t* dl = (uint32_t*)(smc + OFF_V + VLO_O + tid * 80);
            #pragma unroll
            for (int i = 0; i < 8; i++) {
                float4 t = p4[i];
                __nv_bfloat16 h0,l0,h1,l1,h2,l2,h3,l3;
                split1(t.x, h0, l0); split1(t.y, h1, l1);
                split1(t.z, h2, l2); split1(t.w, h3, l3);
                dh[2*i]   = pack2(h0, h1); dh[2*i+1] = pack2(h2, h3);
                dl[2*i]   = pack2(l0, l1); dl[2*i+1] = pack2(l2, l3);
            }
        }
    }
    __syncthreads();

    // ---- S = Q' K'^T + bias + mask  (81 units of m16 x n16) ----
    const float* bi = g_bias + (size_t)h * NTOK * NTOK;
    const float* mk = mask + (size_t)w * NTOK * NTOK;
    uint32_t a_lane = (uint32_t)((lane & 15) * 80 + ((lane >> 4) & 1) * 16);
    uint32_t b_lane = (uint32_t)(((lane & 7) + ((lane & 16) >> 1)) * 80 + ((lane & 8) << 1));

    for (int u = wid; u < 81; u += 8) {
        int mt = u / 9, np = u - mt * 9;
        float c[8] = {};
        #pragma unroll
        for (int ks = 0; ks < 2; ks++) {
            uint32_t ah[4], al[4], bh_[4], bl_[4];
            uint32_t abase = sb + OFF_R + (uint32_t)(mt * 16 * 80) + a_lane + (uint32_t)(ks * 32);
            uint32_t bbase = sb + OFF_R + (uint32_t)(np * 16 * 80) + b_lane + (uint32_t)(ks * 32);
            ldsm4(ah,  abase + QHI_O);
            ldsm4(al,  abase + QLO_O);
            ldsm4(bh_, bbase + KHI_O);
            ldsm4(bl_, bbase + KLO_O);
            mma16816(c,     ah, &bh_[0]);
            mma16816(c + 4, ah, &bh_[2]);
            mma16816(c,     ah, &bl_[0]);
            mma16816(c + 4, ah, &bl_[2]);
            mma16816(c,     al, &bh_[0]);
            mma16816(c + 4, al, &bh_[2]);
        }
        int r0 = mt * 16 + (lane >> 2);
        int c0 = np * 16 + ((lane & 3) << 1);
        #pragma unroll
        for (int half = 0; half < 2; half++) {
            int r = r0 + half * 8;
            #pragma unroll
            for (int nt = 0; nt < 2; nt++) {
                int cc = c0 + nt * 8;
                float2 bv = *(const float2*)(bi + r * NTOK + cc);
                float2 mv = *(const float2*)(mk + r * NTOK + cc);
                Ssm[r * SST + cc]     = c[nt*4 + 2*half]     + bv.x + mv.x;
                Ssm[r * SST + cc + 1] = c[nt*4 + 2*half + 1] + bv.y + mv.y;
            }
        }
    }
    __syncthreads();

    // ---- softmax rows; emit unnormalized exp(P) as bf16 hi/lo ----
    if (tid < NTOK) {
        const float* srow = Ssm + tid * SST;
        float mx = -1e30f;
        for (int cc = 0; cc < NTOK; cc++) mx = fmaxf(mx, srow[cc]);
        float s = 0.f;
        uint32_t* ph = (uint32_t*)(smc + OFF_R + PHI_O + tid * PSTR);
        uint32_t* pl = (uint32_t*)(smc + OFF_R + PLO_O + tid * PSTR);
        for (int cc = 0; cc < NTOK; cc += 2) {
            float e0 = __expf(srow[cc]     - mx);
            float e1 = __expf(srow[cc + 1] - mx);
            s += e0 + e1;
            __nv_bfloat16 h0,l0,h1,l1;
            split1(e0, h0, l0); split1(e1, h1, l1);
            ph[cc >> 1] = pack2(h0, h1);
            pl[cc >> 1] = pack2(l0, l1);
        }
        rsum[tid] = 1.0f / s;
    }
    __syncthreads();

    // ---- O = P V  (18 units of m16 x n16, k = 144 = 9 x 16) ----
    uint32_t pa_lane = (uint32_t)((lane & 15) * PSTR + ((lane >> 4) & 1) * 16);
    uint32_t vb_lane = (uint32_t)((lane & 15) * 80 + ((lane >> 4) & 1) * 16);

    for (int u = wid; u < 18; u += 8) {
        int mt = u >> 1, np = u & 1;
        float c[8] = {};
        #pragma unroll
        for (int ks = 0; ks < 9; ks++) {
            uint32_t pa[4], pb[4], va[4], vb[4];
            uint32_t pbase = sb + OFF_R + (uint32_t)(mt * 16 * PSTR) + pa_lane + (uint32_t)(ks * 32);
            uint32_t vbase = sb + OFF_V + (uint32_t)(ks * 16 * 80) + (uint32_t)(np * 32) + vb_lane;
            ldsm4(pa, pbase + PHI_O);
            ldsm4(pb, pbase + PLO_O);
            ldsm4t(va, vbase + VHI_O);
            ldsm4t(vb, vbase + VLO_O);
            mma16816(c,     pa, &va[0]);
            mma16816(c + 4, pa, &va[2]);
            mma16816(c,     pa, &vb[0]);
            mma16816(c + 4, pa, &vb[2]);
            mma16816(c,     pb, &va[0]);
            mma16816(c + 4, pb, &va[2]);
        }
        int r0 = mt * 16 + (lane >> 2);
        int d0 = np * 16 + ((lane & 3) << 1);
        #pragma unroll
        for (int half = 0; half < 2; half++) {
            int r = r0 + half * 8;
            float ri = rsum[r];
            size_t rowo = ((size_t)b * NTOK + r) * CDIM + h * HD;
            #pragma unroll
            for (int nt = 0; nt < 2; nt++) {
                int d = d0 + nt * 8;
                float v0 = c[nt*4 + 2*half]     * ri;
                float v1 = c[nt*4 + 2*half + 1] * ri;
                __nv_bfloat16 h0,l0,h1,l1;
                split1(v0, h0, l0); split1(v1, h1, l1);
                *(uint32_t*)(g_aohi + rowo + d) = pack2(h0, h1);
                *(uint32_t*)(g_aolo + rowo + d) = pack2(l0, l1);
            }
        }
    }
}

// ---------------- launcher ----------------
extern "C" void kernel_launch(void* const* d_in, const int* in_sizes, int n_in,
                              void* d_out, int out_size) {
    const float* x           = (const float*)d_in[0];
    const float* mask        = (const float*)d_in[1];
    const float* qkv_w       = (const float*)d_in[2];
    const float* qkv_b       = (const float*)d_in[3];
    const float* logit_scale = (const float*)d_in[4];
    const float* cpb_w1      = (const float*)d_in[5];
    const float* cpb_b1      = (const float*)d_in[6];
    const float* cpb_w2      = (const float*)d_in[7];
    const float* proj_w      = (const float*)d_in[8];
    const float* proj_b      = (const float*)d_in[9];
    float* out = (float*)d_out;

    cudaFuncSetAttribute(attn_mma_kernel, cudaFuncAttributeMaxDynamicSharedMemorySize, ATTN_SMEM);
    cudaFuncSetAttribute(mma_gemm_kernel, cudaFuncAttributeMaxDynamicSharedMemorySize, GEMM_SMEM);

    __nv_bfloat16 *p_xhi, *p_xlo, *p_wqhi, *p_wqlo, *p_wphi, *p_wplo;
    cudaGetSymbolAddress((void**)&p_xhi, g_xhi);
    cudaGetSymbolAddress((void**)&p_xlo, g_xlo);
    cudaGetSymbolAddress((void**)&p_wqhi, g_wqhi);
    cudaGetSymbolAddress((void**)&p_wqlo, g_wqlo);
    cudaGetSymbolAddress((void**)&p_wphi, g_wphi);
    cudaGetSymbolAddress((void**)&p_wplo, g_wplo);
    __nv_bfloat16 *p_aohi, *p_aolo;
    cudaGetSymbolAddress((void**)&p_aohi, g_aohi);
    cudaGetSymbolAddress((void**)&p_aolo, g_aolo);

    conv_split_kernel<<<(MROWS*CDIM/4 + 255)/256, 256>>>(x, p_xhi, p_xlo, MROWS*CDIM/4);
    conv_split_kernel<<<(3*CDIM*CDIM/4 + 255)/256, 256>>>(qkv_w, p_wqhi, p_wqlo, 3*CDIM*CDIM/4);
    conv_split_kernel<<<(CDIM*CDIM/4 + 255)/256, 256>>>(proj_w, p_wphi, p_wplo, CDIM*CDIM/4);
    bias_tab_kernel<<<529, 512>>>(cpb_w1, cpb_b1, cpb_w2);
    bias_gather_kernel<<<(NH*NTOK*NTOK + 255)/256, 256>>>();
    // QKV: C[73728, 1152] = x @ qkv_w^T + qkv_b -> scatter q/k/v
    mma_gemm_kernel<<<dim3(9, 576), 256, GEMM_SMEM>>>(p_xhi, p_xlo, p_wqhi, p_wqlo, qkv_b, nullptr, 1);
    attn_mma_kernel<<<BWIN*NH, 256, ATTN_SMEM>>>(mask, logit_scale);
    // proj: out[73728, 384] = attout @ proj_w^T + proj_b
    mma_gemm_kernel<<<dim3(3, 576), 256, GEMM_SMEM>>>(p_aohi, p_aolo, p_wphi, p_wplo, proj_b, out, 0);
}

// round 13
// speedup vs baseline: 2.2354x; 1.0015x over previous
#include <cuda_runtime.h>
#include <cuda_bf16.h>
#include <math.h>
#include <stdint.h>

#define WSD 12
#define NTOK 144
#define CDIM 384
#define NH 12
#define HD 32
#define NWIN 4
#define BWIN 512
#define MROWS (BWIN*NTOK)   // 73728

// ---------------- scratch (no allocations allowed) ----------------
__device__ float g_q[(size_t)BWIN*NH*NTOK*HD];
__device__ float g_k[(size_t)BWIN*NH*NTOK*HD];
__device__ float g_v[(size_t)BWIN*NH*NTOK*HD];
__device__ __nv_bfloat16 g_xhi[(size_t)MROWS*CDIM];
__device__ __nv_bfloat16 g_xlo[(size_t)MROWS*CDIM];
__device__ __nv_bfloat16 g_aohi[(size_t)MROWS*CDIM];
__device__ __nv_bfloat16 g_aolo[(size_t)MROWS*CDIM];
__device__ __nv_bfloat16 g_wqhi[3*CDIM*CDIM];
__device__ __nv_bfloat16 g_wqlo[3*CDIM*CDIM];
__device__ __nv_bfloat16 g_wphi[CDIM*CDIM];
__device__ __nv_bfloat16 g_wplo[CDIM*CDIM];
__device__ float g_tab[529*NH];
__device__ float g_bias[NH*NTOK*NTOK];

// ================= helpers =================
__device__ __forceinline__ uint32_t smem_u32(const void* p) {
    uint32_t a;
    asm("{ .reg .u64 t; cvta.to.shared.u64 t, %1; cvt.u32.u64 %0, t; }" : "=r"(a) : "l"(p));
    return a;
}
__device__ __forceinline__ void ldsm4(uint32_t* r, uint32_t addr) {
    asm volatile("ldmatrix.sync.aligned.m8n8.x4.shared.b16 {%0,%1,%2,%3}, [%4];"
        : "=r"(r[0]), "=r"(r[1]), "=r"(r[2]), "=r"(r[3]) : "r"(addr));
}
__device__ __forceinline__ void ldsm4t(uint32_t* r, uint32_t addr) {
    asm volatile("ldmatrix.sync.aligned.m8n8.x4.trans.shared.b16 {%0,%1,%2,%3}, [%4];"
        : "=r"(r[0]), "=r"(r[1]), "=r"(r[2]), "=r"(r[3]) : "r"(addr));
}
__device__ __forceinline__ void mma16816(float* c, const uint32_t* a, const uint32_t* b) {
    asm volatile("mma.sync.aligned.m16n8k16.row.col.f32.bf16.bf16.f32 "
        "{%0,%1,%2,%3}, {%4,%5,%6,%7}, {%8,%9}, {%0,%1,%2,%3};"
        : "+f"(c[0]), "+f"(c[1]), "+f"(c[2]), "+f"(c[3])
        : "r"(a[0]), "r"(a[1]), "r"(a[2]), "r"(a[3]), "r"(b[0]), "r"(b[1]));
}
__device__ __forceinline__ void split1(float v, __nv_bfloat16& h, __nv_bfloat16& l) {
    h = __float2bfloat16(v);
    l = __float2bfloat16(v - __bfloat162float(h));
}
__device__ __forceinline__ uint32_t pack2(__nv_bfloat16 a, __nv_bfloat16 b) {
    return (uint32_t)__bfloat16_as_ushort(a) | ((uint32_t)__bfloat16_as_ushort(b) << 16);
}
#define CP_ASYNC16(dst, src) \
    asm volatile("cp.async.cg.shared.global [%0], [%1], 16;" :: "r"(dst), "l"(src) : "memory")
#define CP_COMMIT() asm volatile("cp.async.commit_group;" ::: "memory")
#define CP_WAIT1() asm volatile("cp.async.wait_group 1;" ::: "memory")
#define CP_WAIT0() asm volatile("cp.async.wait_group 0;" ::: "memory")

// ---------------- fp32 -> bf16 hi/lo split ----------------
__global__ void conv_split_kernel(const float* __restrict__ src,
                                  __nv_bfloat16* __restrict__ hi,
                                  __nv_bfloat16* __restrict__ lo, int n4) {
    int i = blockIdx.x * blockDim.x + threadIdx.x;
    if (i >= n4) return;
    float4 v = ((const float4*)src)[i];
    __nv_bfloat16 h0, l0, h1, l1, h2, l2, h3, l3;
    split1(v.x, h0, l0); split1(v.y, h1, l1);
    split1(v.z, h2, l2); split1(v.w, h3, l3);
    uint2 ph, pl;
    ph.x = pack2(h0, h1); ph.y = pack2(h2, h3);
    pl.x = pack2(l0, l1); pl.y = pack2(l2, l3);
    *(uint2*)(hi + 4*(size_t)i) = ph;
    *(uint2*)(lo + 4*(size_t)i) = pl;
}

// ================= mma.sync GEMM (cp.async double-buffered) =================
// Inner MMA order: product phase OUTER (hh, hl, lh) -> same-accumulator reuse
// distance of 16 MMAs instead of 2, to cover HMMA latency.
#define LDSB 144
#define A_HI 0
#define A_LO 18432
#define B_HI 36864
#define B_LO 55296
#define STAGE 73728
#define GEMM_SMEM (2*STAGE)

__global__ __launch_bounds__(256, 1)
void mma_gemm_kernel(const __nv_bfloat16* __restrict__ Ahi,
                     const __nv_bfloat16* __restrict__ Alo,
                     const __nv_bfloat16* __restrict__ Bhi,
                     const __nv_bfloat16* __restrict__ Blo,
                     const float* __restrict__ bias,
                     float* __restrict__ outp,
                     int qkv_mode)
{
    extern __shared__ char smem[];
    uint32_t sb = smem_u32(smem);
    int tid = threadIdx.x;
    int wid = tid >> 5, lane = tid & 31;
    int wm = wid & 1, wn = wid >> 1;
    int m0 = blockIdx.y * 128, n0 = blockIdx.x * 128;

    float acc[4][4][4] = {};

    uint32_t aoff = (uint32_t)((wm*64 + (lane & 15)) * LDSB + (((lane >> 4) & 1) << 4));
    uint32_t boff = (uint32_t)((wn*32 + (lane & 7) + ((lane & 16) >> 1)) * LDSB + ((lane & 8) << 1));

    int frow = tid >> 3, fc8 = (tid & 7) << 3;
    uint32_t fso = (uint32_t)(frow * LDSB + (fc8 << 1));

    {
        size_t gaB = (size_t)(m0 + frow) * CDIM + fc8;
        size_t gbB = (size_t)(n0 + frow) * CDIM + fc8;
        #pragma unroll
        for (int i = 0; i < 4; i++) {
            uint32_t so = fso + (uint32_t)(i * 32 * LDSB);
            size_t ga = gaB + (size_t)i * 32 * CDIM;
            size_t gb = gbB + (size_t)i * 32 * CDIM;
            CP_ASYNC16(sb + A_HI + so, Ahi + ga);
            CP_ASYNC16(sb + A_LO + so, Alo + ga);
            CP_ASYNC16(sb + B_HI + so, Bhi + gb);
            CP_ASYNC16(sb + B_LO + so, Blo + gb);
        }
        CP_COMMIT();
    }

    for (int c = 0; c < 6; c++) {
        uint32_t cur = sb + (uint32_t)((c & 1) * STAGE);
        if (c < 5) {
            uint32_t nxt = sb + (uint32_t)(((c + 1) & 1) * STAGE);
            int kc = (c + 1) * 64;
            size_t gaB = (size_t)(m0 + frow) * CDIM + kc + fc8;
            size_t gbB = (size_t)(n0 + frow) * CDIM + kc + fc8;
            #pragma unroll
            for (int i = 0; i < 4; i++) {
                uint32_t so = fso + (uint32_t)(i * 32 * LDSB);
                size_t ga = gaB + (size_t)i * 32 * CDIM;
                size_t gb = gbB + (size_t)i * 32 * CDIM;
                CP_ASYNC16(nxt + A_HI + so, Ahi + ga);
                CP_ASYNC16(nxt + A_LO + so, Alo + ga);
                CP_ASYNC16(nxt + B_HI + so, Bhi + gb);
                CP_ASYNC16(nxt + B_LO + so, Blo + gb);
            }
            CP_COMMIT();
            CP_WAIT1();
        } else {
            CP_WAIT0();
        }
        __syncthreads();

        #pragma unroll
        for (int ks = 0; ks < 4; ks++) {
            uint32_t ahi[4][4], alo[4][4], bhi[2][4], blo[2][4];
            uint32_t kb = (uint32_t)(ks << 5);
            #pragma unroll
            for (int mt = 0; mt < 4; mt++) {
                ldsm4(ahi[mt], cur + A_HI + aoff + mt*(16*LDSB) + kb);
                ldsm4(alo[mt], cur + A_LO + aoff + mt*(16*LDSB) + kb);
            }
            #pragma unroll
            for (int tp = 0; tp < 2; tp++) {
                ldsm4(bhi[tp], cur + B_HI + boff + tp*(16*LDSB) + kb);
                ldsm4(blo[tp], cur + B_LO + boff + tp*(16*LDSB) + kb);
            }
            // phase 1: hi * hi  (each accumulator touched exactly once)
            #pragma unroll
            for (int mt = 0; mt < 4; mt++) {
                #pragma unroll
                for (int tp = 0; tp < 2; tp++) {
                    mma16816(acc[mt][2*tp],   ahi[mt], &bhi[tp][0]);
                    mma16816(acc[mt][2*tp+1], ahi[mt], &bhi[tp][2]);
                }
            }
            // phase 2: hi * lo
            #pragma unroll
            for (int mt = 0; mt < 4; mt++) {
                #pragma unroll
                for (int tp = 0; tp < 2; tp++) {
                    mma16816(acc[mt][2*tp],   ahi[mt], &blo[tp][0]);
                    mma16816(acc[mt][2*tp+1], ahi[mt], &blo[tp][2]);
                }
            }
            // phase 3: lo * hi
            #pragma unroll
            for (int mt = 0; mt < 4; mt++) {
                #pragma unroll
                for (int tp = 0; tp < 2; tp++) {
                    mma16816(acc[mt][2*tp],   alo[mt], &bhi[tp][0]);
                    mma16816(acc[mt][2*tp+1], alo[mt], &bhi[tp][2]);
                }
            }
        }
        __syncthreads();
    }

    int colw = n0 + wn * 32;
    float* dstq = nullptr;
    int which = 0, h = 0;
    if (qkv_mode) {
        which = colw / CDIM;
        int rem = colw - which * CDIM;
        h = rem >> 5;
        dstq = (which == 0) ? g_q : ((which == 1) ? g_k : g_v);
    }
    #pragma unroll
    for (int mt = 0; mt < 4; mt++) {
        int r0 = m0 + wm*64 + mt*16 + (lane >> 2);
        #pragma unroll
        for (int half = 0; half < 2; half++) {
            int r = r0 + half * 8;
            int b = r / NTOK, nn = r - b * NTOK;
            #pragma unroll
            for (int nt = 0; nt < 4; nt++) {
                int col = colw + nt*8 + ((lane & 3) << 1);
                float2 o;
                o.x = acc[mt][nt][2*half]   + bias[col];
                o.y = acc[mt][nt][2*half+1] + bias[col+1];
                if (qkv_mode) {
                    int d = col & 31;
                    *(float2*)(dstq + (((size_t)b * NH + h) * NTOK + nn) * HD + d) = o;
                } else {
                    *(float2*)(outp + (size_t)r * CDIM + col) = o;
                }
            }
        }
    }
}

// ---------------- CPB-MLP bias table: (529, 12) ----------------
__global__ void bias_tab_kernel(const float* __restrict__ w1,
                                const float* __restrict__ b1,
                                const float* __restrict__ w2) {
    __shared__ float hid[512];
    int t = blockIdx.x;
    int ti = t / 23, tj = t % 23;
    float ra = (float)(ti - 11) * (12.0f / 11.0f);
    float rb = (float)(tj - 11) * (12.0f / 11.0f);
    float sa = (ra > 0.f) ? 1.f : ((ra < 0.f) ? -1.f : 0.f);
    float sb = (rb > 0.f) ? 1.f : ((rb < 0.f) ? -1.f : 0.f);
    float t0 = sa * log2f(fabsf(ra) + 1.0f) * (1.0f / 3.0f);
    float t1 = sb * log2f(fabsf(rb) + 1.0f) * (1.0f / 3.0f);
    int j = threadIdx.x;
    hid[j] = fmaxf(t0 * w1[2*j] + t1 * w1[2*j+1] + b1[j], 0.0f);
    __syncthreads();
    int wid = j >> 5, lane = j & 31;
    if (wid < NH) {
        const float* wr = w2 + wid * 512;
        float s = 0.f;
        #pragma unroll
        for (int q = 0; q < 16; q++) s += hid[lane + 32*q] * wr[lane + 32*q];
        #pragma unroll
        for (int o = 16; o; o >>= 1) s += __shfl_xor_sync(0xFFFFFFFFu, s, o);
        if (lane == 0) g_tab[t * NH + wid] = s;
    }
}

// ---------------- gather + 16*sigmoid into (h, n, m) ----------------
__global__ void bias_gather_kernel() {
    int g = blockIdx.x * blockDim.x + threadIdx.x;
    if (g >= NH * NTOK * NTOK) return;
    int h = g / (NTOK * NTOK);
    int r = g % (NTOK * NTOK);
    int n = r / NTOK, m = r % NTOK;
    int dr = n / WSD - m / WSD + 11;
    int dc = n % WSD - m % WSD + 11;
    float v = g_tab[(dr * 23 + dc) * NH + h];
    g_bias[g] = 16.0f / (1.0f + expf(-v));
}

// ================= tensor-core attention: one CTA per (b,h) =================
#define SST 148
#define OFF_R 85248
#define QHI_O 0
#define QLO_O 11520
#define KHI_O 23040
#define KLO_O 34560
#define PSTR 304
#define PHI_O 0
#define PLO_O 43776
#define OFF_V 172800
#define VHI_O 0
#define VLO_O 11520
#define OFF_SUM 195840
#define ATTN_SMEM 196416

__global__ __launch_bounds__(256, 1) void attn_mma_kernel(
    const float* __restrict__ mask, const float* __restrict__ logit_scale) {
    extern __shared__ char smc[];
    float* Ssm  = (float*)smc;
    float* rsum = (float*)(smc + OFF_SUM);
    uint32_t sb = smem_u32(smc);

    int bh = blockIdx.x;
    int b = bh / NH, h = bh - b * NH;
    int w = b & 3;
    const float* gq = g_q + (size_t)bh * NTOK * HD;
    const float* gk = g_k + (size_t)bh * NTOK * HD;
    const float* gv = g_v + (size_t)bh * NTOK * HD;
    int tid = threadIdx.x, wid = tid >> 5, lane = tid & 31;

    float sc = expf(fminf(logit_scale[h], 4.6051702f));  // ln(100)

    if (tid < NTOK) {
        {
            const float4* p4 = (const float4*)(gq + tid * HD);
            float4 t[8]; float s = 0.f;
            #pragma unroll
            for (int i = 0; i < 8; i++) {
                t[i] = p4[i];
                s += t[i].x*t[i].x + t[i].y*t[i].y + t[i].z*t[i].z + t[i].w*t[i].w;
            }
            float qi = sc / fmaxf(sqrtf(s), 1e-12f);
            uint32_t* dh = (uint32_t*)(smc + OFF_R + QHI_O + tid * 80);
            uint32_t* dl = (uint32_t*)(smc + OFF_R + QLO_O + tid * 80);
            #pragma unroll
            for (int i = 0; i < 8; i++) {
                __nv_bfloat16 h0,l0,h1,l1,h2,l2,h3,l3;
                split1(t[i].x*qi, h0, l0); split1(t[i].y*qi, h1, l1);
                split1(t[i].z*qi, h2, l2); split1(t[i].w*qi, h3, l3);
                dh[2*i]   = pack2(h0, h1); dh[2*i+1] = pack2(h2, h3);
                dl[2*i]   = pack2(l0, l1); dl[2*i+1] = pack2(l2, l3);
            }
        }
        {
            const float4* p4 = (const float4*)(gk + tid * HD);
            float4 t[8]; float s = 0.f;
            #pragma unroll
            for (int i = 0; i < 8; i++) {
                t[i] = p4[i];
                s += t[i].x*t[i].x + t[i].y*t[i].y + t[i].z*t[i].z + t[i].w*t[i].w;
            }
            float ki = 1.0f / fmaxf(sqrtf(s), 1e-12f);
            uint32_t* dh = (uint32_t*)(smc + OFF_R + KHI_O + tid * 80);
            uint32_t* dl = (uint32_t*)(smc + OFF_R + KLO_O + tid * 80);
            #pragma unroll
            for (int i = 0; i < 8; i++) {
                __nv_bfloat16 h0,l0,h1,l1,h2,l2,h3,l3;
                split1(t[i].x*ki, h0, l0); split1(t[i].y*ki, h1, l1);
                split1(t[i].z*ki, h2, l2); split1(t[i].w*ki, h3, l3);
                dh[2*i]   = pack2(h0, h1); dh[2*i+1] = pack2(h2, h3);
                dl[2*i]   = pack2(l0, l1); dl[2*i+1] = pack2(l2, l3);
            }
        }
        {
            const float4* p4 = (const float4*)(gv + tid * HD);
            uint32_t* dh = (uint32_t*)(smc + OFF_V + VHI_O + tid * 80);
            uint32_t* dl = (uint32_t*)(smc + OFF_V + VLO_O + tid * 80);
            #pragma unroll
            for (int i = 0; i < 8; i++) {
                float4 t = p4[i];
                __nv_bfloat16 h0,l0,h1,l1,h2,l2,h3,l3;
                split1(t.x, h0, l0); split1(t.y, h1, l1);
                split1(t.z, h2, l2); split1(t.w, h3, l3);
                dh[2*i]   = pack2(h0, h1); dh[2*i+1] = pack2(h2, h3);
                dl[2*i]   = pack2(l0, l1); dl[2*i+1] = pack2(l2, l3);
            }
        }
    }
    __syncthreads();

    // ---- S = Q' K'^T + bias + mask ----
    const float* bi = g_bias + (size_t)h * NTOK * NTOK;
    const float* mk = mask + (size_t)w * NTOK * NTOK;
    uint32_t a_lane = (uint32_t)((lane & 15) * 80 + ((lane >> 4) & 1) * 16);
    uint32_t b_lane = (uint32_t)(((lane & 7) + ((lane & 16) >> 1)) * 80 + ((lane & 8) << 1));

    for (int u = wid; u < 81; u += 8) {
        int mt = u / 9, np = u - mt * 9;
        float c[8] = {};
        #pragma unroll
        for (int ks = 0; ks < 2; ks++) {
            uint32_t ah[4], al[4], bh_[4], bl_[4];
            uint32_t abase = sb + OFF_R + (uint32_t)(mt * 16 * 80) + a_lane + (uint32_t)(ks * 32);
            uint32_t bbase = sb + OFF_R + (uint32_t)(np * 16 * 80) + b_lane + (uint32_t)(ks * 32);
            ldsm4(ah,  abase + QHI_O);
            ldsm4(al,  abase + QLO_O);
            ldsm4(bh_, bbase + KHI_O);
            ldsm4(bl_, bbase + KLO_O);
            mma16816(c,     ah, &bh_[0]);
            mma16816(c + 4, ah, &bh_[2]);
            mma16816(c,     ah, &bl_[0]);
            mma16816(c + 4, ah, &bl_[2]);
            mma16816(c,     al, &bh_[0]);
            mma16816(c + 4, al, &bh_[2]);
        }
        int r0 = mt * 16 + (lane >> 2);
        int c0 = np * 16 + ((lane & 3) << 1);
        #pragma unroll
        for (int half = 0; half < 2; half++) {
            int r = r0 + half * 8;
            #pragma unroll
            for (int nt = 0; nt < 2; nt++) {
                int cc = c0 + nt * 8;
                float2 bv = *(const float2*)(bi + r * NTOK + cc);
                float2 mv = *(const float2*)(mk + r * NTOK + cc);
                Ssm[r * SST + cc]     = c[nt*4 + 2*half]     + bv.x + mv.x;
                Ssm[r * SST + cc + 1] = c[nt*4 + 2*half + 1] + bv.y + mv.y;
            }
        }
    }
    __syncthreads();

    // ---- softmax rows; emit unnormalized exp(P) as bf16 hi/lo ----
    if (tid < NTOK) {
        const float* srow = Ssm + tid * SST;
        float mx = -1e30f;
        for (int cc = 0; cc < NTOK; cc++) mx = fmaxf(mx, srow[cc]);
        float s = 0.f;
        uint32_t* ph = (uint32_t*)(smc + OFF_R + PHI_O + tid * PSTR);
        uint32_t* pl = (uint32_t*)(smc + OFF_R + PLO_O + tid * PSTR);
        for (int cc = 0; cc < NTOK; cc += 2) {
            float e0 = __expf(srow[cc]     - mx);
            float e1 = __expf(srow[cc + 1] - mx);
            s += e0 + e1;
            __nv_bfloat16 h0,l0,h1,l1;
            split1(e0, h0, l0); split1(e1, h1, l1);
            ph[cc >> 1] = pack2(h0, h1);
            pl[cc >> 1] = pack2(l0, l1);
        }
        rsum[tid] = 1.0f / s;
    }
    __syncthreads();

    // ---- O = P V ----
    uint32_t pa_lane = (uint32_t)((lane & 15) * PSTR + ((lane >> 4) & 1) * 16);
    uint32_t vb_lane = (uint32_t)((lane & 15) * 80 + ((lane >> 4) & 1) * 16);

    for (int u = wid; u < 18; u += 8) {
        int mt = u >> 1, np = u & 1;
        float c[8] = {};
        #pragma unroll
        for (int ks = 0; ks < 9; ks++) {
            uint32_t pa[4], pb[4], va[4], vb[4];
            uint32_t pbase = sb + OFF_R + (uint32_t)(mt * 16 * PSTR) + pa_lane + (uint32_t)(ks * 32);
            uint32_t vbase = sb + OFF_V + (uint32_t)(ks * 16 * 80) + (uint32_t)(np * 32) + vb_lane;
            ldsm4(pa, pbase + PHI_O);
            ldsm4(pb, pbase + PLO_O);
            ldsm4t(va, vbase + VHI_O);
            ldsm4t(vb, vbase + VLO_O);
            mma16816(c,     pa, &va[0]);
            mma16816(c + 4, pa, &va[2]);
            mma16816(c,     pa, &vb[0]);
            mma16816(c + 4, pa, &vb[2]);
            mma16816(c,     pb, &va[0]);
            mma16816(c + 4, pb, &va[2]);
        }
        int r0 = mt * 16 + (lane >> 2);
        int d0 = np * 16 + ((lane & 3) << 1);
        #pragma unroll
        for (int half = 0; half < 2; half++) {
            int r = r0 + half * 8;
            float ri = rsum[r];
            size_t rowo = ((size_t)b * NTOK + r) * CDIM + h * HD;
            #pragma unroll
            for (int nt = 0; nt < 2; nt++) {
                int d = d0 + nt * 8;
                float v0 = c[nt*4 + 2*half]     * ri;
                float v1 = c[nt*4 + 2*half + 1] * ri;
                __nv_bfloat16 h0,l0,h1,l1;
                split1(v0, h0, l0); split1(v1, h1, l1);
                *(uint32_t*)(g_aohi + rowo + d) = pack2(h0, h1);
                *(uint32_t*)(g_aolo + rowo + d) = pack2(l0, l1);
            }
        }
    }
}

// ---------------- launcher ----------------
extern "C" void kernel_launch(void* const* d_in, const int* in_sizes, int n_in,
                              void* d_out, int out_size) {
    const float* x           = (const float*)d_in[0];
    const float* mask        = (const float*)d_in[1];
    const float* qkv_w       = (const float*)d_in[2];
    const float* qkv_b       = (const float*)d_in[3];
    const float* logit_scale = (const float*)d_in[4];
    const float* cpb_w1      = (const float*)d_in[5];
    const float* cpb_b1      = (const float*)d_in[6];
    const float* cpb_w2      = (const float*)d_in[7];
    const float* proj_w      = (const float*)d_in[8];
    const float* proj_b      = (const float*)d_in[9];
    float* out = (float*)d_out;

    cudaFuncSetAttribute(attn_mma_kernel, cudaFuncAttributeMaxDynamicSharedMemorySize, ATTN_SMEM);
    cudaFuncSetAttribute(mma_gemm_kernel, cudaFuncAttributeMaxDynamicSharedMemorySize, GEMM_SMEM);

    __nv_bfloat16 *p_xhi, *p_xlo, *p_wqhi, *p_wqlo, *p_wphi, *p_wplo;
    cudaGetSymbolAddress((void**)&p_xhi, g_xhi);
    cudaGetSymbolAddress((void**)&p_xlo, g_xlo);
    cudaGetSymbolAddress((void**)&p_wqhi, g_wqhi);
    cudaGetSymbolAddress((void**)&p_wqlo, g_wqlo);
    cudaGetSymbolAddress((void**)&p_wphi, g_wphi);
    cudaGetSymbolAddress((void**)&p_wplo, g_wplo);
    __nv_bfloat16 *p_aohi, *p_aolo;
    cudaGetSymbolAddress((void**)&p_aohi, g_aohi);
    cudaGetSymbolAddress((void**)&p_aolo, g_aolo);

    conv_split_kernel<<<(MROWS*CDIM/4 + 255)/256, 256>>>(x, p_xhi, p_xlo, MROWS*CDIM/4);
    conv_split_kernel<<<(3*CDIM*CDIM/4 + 255)/256, 256>>>(qkv_w, p_wqhi, p_wqlo, 3*CDIM*CDIM/4);
    conv_split_kernel<<<(CDIM*CDIM/4 + 255)/256, 256>>>(proj_w, p_wphi, p_wplo, CDIM*CDIM/4);
    bias_tab_kernel<<<529, 512>>>(cpb_w1, cpb_b1, cpb_w2);
    bias_gather_kernel<<<(NH*NTOK*NTOK + 255)/256, 256>>>();
    // QKV: C[73728, 1152] = x @ qkv_w^T + qkv_b -> scatter q/k/v
    mma_gemm_kernel<<<dim3(9, 576), 256, GEMM_SMEM>>>(p_xhi, p_xlo, p_wqhi, p_wqlo, qkv_b, nullptr, 1);
    attn_mma_kernel<<<BWIN*NH, 256, ATTN_SMEM>>>(mask, logit_scale);
    // proj: out[73728, 384] = attout @ proj_w^T + proj_b
    mma_gemm_kernel<<<dim3(3, 576), 256, GEMM_SMEM>>>(p_aohi, p_aolo, p_wphi, p_wplo, proj_b, out, 0);
}

// round 14
// speedup vs baseline: 2.7310x; 1.2217x over previous
#include <cuda_runtime.h>
#include <cuda_bf16.h>
#include <cuda_fp16.h>
#include <math.h>
#include <stdint.h>

#define WSD 12
#define NTOK 144
#define CDIM 384
#define NH 12
#define HD 32
#define NWIN 4
#define BWIN 512
#define MROWS (BWIN*NTOK)   // 73728

// ---------------- scratch (no allocations allowed) ----------------
__device__ float g_q[(size_t)BWIN*NH*NTOK*HD];
__device__ float g_k[(size_t)BWIN*NH*NTOK*HD];
__device__ float g_v[(size_t)BWIN*NH*NTOK*HD];
__device__ __half g_xhi[(size_t)MROWS*CDIM];
__device__ __half g_xlo[(size_t)MROWS*CDIM];
__device__ __half g_aohi[(size_t)MROWS*CDIM];
__device__ __half g_aolo[(size_t)MROWS*CDIM];
__device__ __half g_wqhi[3*CDIM*CDIM];
__device__ __half g_wphi[CDIM*CDIM];
__device__ float g_tab[529*NH];
__device__ float g_bias[NH*NTOK*NTOK];

// ================= helpers =================
__device__ __forceinline__ uint32_t smem_u32(const void* p) {
    uint32_t a;
    asm("{ .reg .u64 t; cvta.to.shared.u64 t, %1; cvt.u32.u64 %0, t; }" : "=r"(a) : "l"(p));
    return a;
}
__device__ __forceinline__ void ldsm4(uint32_t* r, uint32_t addr) {
    asm volatile("ldmatrix.sync.aligned.m8n8.x4.shared.b16 {%0,%1,%2,%3}, [%4];"
        : "=r"(r[0]), "=r"(r[1]), "=r"(r[2]), "=r"(r[3]) : "r"(addr));
}
__device__ __forceinline__ void ldsm4t(uint32_t* r, uint32_t addr) {
    asm volatile("ldmatrix.sync.aligned.m8n8.x4.trans.shared.b16 {%0,%1,%2,%3}, [%4];"
        : "=r"(r[0]), "=r"(r[1]), "=r"(r[2]), "=r"(r[3]) : "r"(addr));
}
// bf16 MMA (attention)
__device__ __forceinline__ void mma16816(float* c, const uint32_t* a, const uint32_t* b) {
    asm volatile("mma.sync.aligned.m16n8k16.row.col.f32.bf16.bf16.f32 "
        "{%0,%1,%2,%3}, {%4,%5,%6,%7}, {%8,%9}, {%0,%1,%2,%3};"
        : "+f"(c[0]), "+f"(c[1]), "+f"(c[2]), "+f"(c[3])
        : "r"(a[0]), "r"(a[1]), "r"(a[2]), "r"(a[3]), "r"(b[0]), "r"(b[1]));
}
// fp16 MMA (GEMMs)
__device__ __forceinline__ void mma16816h(float* c, const uint32_t* a, const uint32_t* b) {
    asm volatile("mma.sync.aligned.m16n8k16.row.col.f32.f16.f16.f32 "
        "{%0,%1,%2,%3}, {%4,%5,%6,%7}, {%8,%9}, {%0,%1,%2,%3};"
        : "+f"(c[0]), "+f"(c[1]), "+f"(c[2]), "+f"(c[3])
        : "r"(a[0]), "r"(a[1]), "r"(a[2]), "r"(a[3]), "r"(b[0]), "r"(b[1]));
}
__device__ __forceinline__ void split1(float v, __nv_bfloat16& h, __nv_bfloat16& l) {
    h = __float2bfloat16(v);
    l = __float2bfloat16(v - __bfloat162float(h));
}
__device__ __forceinline__ void split1h(float v, __half& h, __half& l) {
    h = __float2half(v);
    l = __float2half(v - __half2float(h));
}
__device__ __forceinline__ uint32_t pack2(__nv_bfloat16 a, __nv_bfloat16 b) {
    return (uint32_t)__bfloat16_as_ushort(a) | ((uint32_t)__bfloat16_as_ushort(b) << 16);
}
__device__ __forceinline__ uint32_t pack2h(__half a, __half b) {
    return (uint32_t)__half_as_ushort(a) | ((uint32_t)__half_as_ushort(b) << 16);
}
#define CP_ASYNC16(dst, src) \
    asm volatile("cp.async.cg.shared.global [%0], [%1], 16;" :: "r"(dst), "l"(src) : "memory")
#define CP_COMMIT() asm volatile("cp.async.commit_group;" ::: "memory")
#define CP_WAIT1() asm volatile("cp.async.wait_group 1;" ::: "memory")
#define CP_WAIT0() asm volatile("cp.async.wait_group 0;" ::: "memory")

// ---------------- fp32 -> fp16 hi/lo split ----------------
__global__ void conv_split_kernel(const float* __restrict__ src,
                                  __half* __restrict__ hi,
                                  __half* __restrict__ lo, int n4) {
    int i = blockIdx.x * blockDim.x + threadIdx.x;
    if (i >= n4) return;
    float4 v = ((const float4*)src)[i];
    __half h0, l0, h1, l1, h2, l2, h3, l3;
    split1h(v.x, h0, l0); split1h(v.y, h1, l1);
    split1h(v.z, h2, l2); split1h(v.w, h3, l3);
    uint2 ph;
    ph.x = pack2h(h0, h1); ph.y = pack2h(h2, h3);
    *(uint2*)(hi + 4*(size_t)i) = ph;
    if (lo) {
        uint2 pl;
        pl.x = pack2h(l0, l1); pl.y = pack2h(l2, l3);
        *(uint2*)(lo + 4*(size_t)i) = pl;
    }
}

// ================= fp16 2-product mma.sync GEMM (cp.async double-buffered) =================
// C = A @ W^T + bias with A = Ahi + Alo (fp16 split), W ~ fp16(W) single.
// Error = A . (W - fp16(W)) ~ 3e-4 relative.
#define LDSB 144
#define A_HI 0
#define A_LO 18432
#define B_HI 36864
#define STAGE 55296
#define GEMM_SMEM (2*STAGE)

__global__ __launch_bounds__(256, 1)
void mma_gemm_kernel(const __half* __restrict__ Ahi,
                     const __half* __restrict__ Alo,
                     const __half* __restrict__ Bhi,
                     const float* __restrict__ bias,
                     float* __restrict__ outp,
                     int qkv_mode)
{
    extern __shared__ char smem[];
    uint32_t sb = smem_u32(smem);
    int tid = threadIdx.x;
    int wid = tid >> 5, lane = tid & 31;
    int wm = wid & 1, wn = wid >> 1;
    int m0 = blockIdx.y * 128, n0 = blockIdx.x * 128;

    float acc[4][4][4] = {};

    uint32_t aoff = (uint32_t)((wm*64 + (lane & 15)) * LDSB + (((lane >> 4) & 1) << 4));
    uint32_t boff = (uint32_t)((wn*32 + (lane & 7) + ((lane & 16) >> 1)) * LDSB + ((lane & 8) << 1));

    int frow = tid >> 3, fc8 = (tid & 7) << 3;
    uint32_t fso = (uint32_t)(frow * LDSB + (fc8 << 1));

    {
        size_t gaB = (size_t)(m0 + frow) * CDIM + fc8;
        size_t gbB = (size_t)(n0 + frow) * CDIM + fc8;
        #pragma unroll
        for (int i = 0; i < 4; i++) {
            uint32_t so = fso + (uint32_t)(i * 32 * LDSB);
            size_t ga = gaB + (size_t)i * 32 * CDIM;
            size_t gb = gbB + (size_t)i * 32 * CDIM;
            CP_ASYNC16(sb + A_HI + so, Ahi + ga);
            CP_ASYNC16(sb + A_LO + so, Alo + ga);
            CP_ASYNC16(sb + B_HI + so, Bhi + gb);
        }
        CP_COMMIT();
    }

    for (int c = 0; c < 6; c++) {
        uint32_t cur = sb + (uint32_t)((c & 1) * STAGE);
        if (c < 5) {
            uint32_t nxt = sb + (uint32_t)(((c + 1) & 1) * STAGE);
            int kc = (c + 1) * 64;
            size_t gaB = (size_t)(m0 + frow) * CDIM + kc + fc8;
            size_t gbB = (size_t)(n0 + frow) * CDIM + kc + fc8;
            #pragma unroll
            for (int i = 0; i < 4; i++) {
                uint32_t so = fso + (uint32_t)(i * 32 * LDSB);
                size_t ga = gaB + (size_t)i * 32 * CDIM;
                size_t gb = gbB + (size_t)i * 32 * CDIM;
                CP_ASYNC16(nxt + A_HI + so, Ahi + ga);
                CP_ASYNC16(nxt + A_LO + so, Alo + ga);
                CP_ASYNC16(nxt + B_HI + so, Bhi + gb);
            }
            CP_COMMIT();
            CP_WAIT1();
        } else {
            CP_WAIT0();
        }
        __syncthreads();

        #pragma unroll
        for (int ks = 0; ks < 4; ks++) {
            uint32_t ahi[4][4], alo[4][4], bhi[2][4];
            uint32_t kb = (uint32_t)(ks << 5);
            #pragma unroll
            for (int mt = 0; mt < 4; mt++) {
                ldsm4(ahi[mt], cur + A_HI + aoff + mt*(16*LDSB) + kb);
                ldsm4(alo[mt], cur + A_LO + aoff + mt*(16*LDSB) + kb);
            }
            #pragma unroll
            for (int tp = 0; tp < 2; tp++) {
                ldsm4(bhi[tp], cur + B_HI + boff + tp*(16*LDSB) + kb);
            }
            // phase 1: ahi * bhi
            #pragma unroll
            for (int mt = 0; mt < 4; mt++) {
                #pragma unroll
                for (int tp = 0; tp < 2; tp++) {
                    mma16816h(acc[mt][2*tp],   ahi[mt], &bhi[tp][0]);
                    mma16816h(acc[mt][2*tp+1], ahi[mt], &bhi[tp][2]);
                }
            }
            // phase 2: alo * bhi
            #pragma unroll
            for (int mt = 0; mt < 4; mt++) {
                #pragma unroll
                for (int tp = 0; tp < 2; tp++) {
                    mma16816h(acc[mt][2*tp],   alo[mt], &bhi[tp][0]);
                    mma16816h(acc[mt][2*tp+1], alo[mt], &bhi[tp][2]);
                }
            }
        }
        __syncthreads();
    }

    int colw = n0 + wn * 32;
    float* dstq = nullptr;
    int which = 0, h = 0;
    if (qkv_mode) {
        which = colw / CDIM;
        int rem = colw - which * CDIM;
        h = rem >> 5;
        dstq = (which == 0) ? g_q : ((which == 1) ? g_k : g_v);
    }
    #pragma unroll
    for (int mt = 0; mt < 4; mt++) {
        int r0 = m0 + wm*64 + mt*16 + (lane >> 2);
        #pragma unroll
        for (int half = 0; half < 2; half++) {
            int r = r0 + half * 8;
            int b = r / NTOK, nn = r - b * NTOK;
            #pragma unroll
            for (int nt = 0; nt < 4; nt++) {
                int col = colw + nt*8 + ((lane & 3) << 1);
                float2 o;
                o.x = acc[mt][nt][2*half]   + bias[col];
                o.y = acc[mt][nt][2*half+1] + bias[col+1];
                if (qkv_mode) {
                    int d = col & 31;
                    *(float2*)(dstq + (((size_t)b * NH + h) * NTOK + nn) * HD + d) = o;
                } else {
                    *(float2*)(outp + (size_t)r * CDIM + col) = o;
                }
            }
        }
    }
}

// ---------------- CPB-MLP bias table: (529, 12) ----------------
__global__ void bias_tab_kernel(const float* __restrict__ w1,
                                const float* __restrict__ b1,
                                const float* __restrict__ w2) {
    __shared__ float hid[512];
    int t = blockIdx.x;
    int ti = t / 23, tj = t % 23;
    float ra = (float)(ti - 11) * (12.0f / 11.0f);
    float rb = (float)(tj - 11) * (12.0f / 11.0f);
    float sa = (ra > 0.f) ? 1.f : ((ra < 0.f) ? -1.f : 0.f);
    float sb = (rb > 0.f) ? 1.f : ((rb < 0.f) ? -1.f : 0.f);
    float t0 = sa * log2f(fabsf(ra) + 1.0f) * (1.0f / 3.0f);
    float t1 = sb * log2f(fabsf(rb) + 1.0f) * (1.0f / 3.0f);
    int j = threadIdx.x;
    hid[j] = fmaxf(t0 * w1[2*j] + t1 * w1[2*j+1] + b1[j], 0.0f);
    __syncthreads();
    int wid = j >> 5, lane = j & 31;
    if (wid < NH) {
        const float* wr = w2 + wid * 512;
        float s = 0.f;
        #pragma unroll
        for (int q = 0; q < 16; q++) s += hid[lane + 32*q] * wr[lane + 32*q];
        #pragma unroll
        for (int o = 16; o; o >>= 1) s += __shfl_xor_sync(0xFFFFFFFFu, s, o);
        if (lane == 0) g_tab[t * NH + wid] = s;
    }
}

// ---------------- gather + 16*sigmoid into (h, n, m) ----------------
__global__ void bias_gather_kernel() {
    int g = blockIdx.x * blockDim.x + threadIdx.x;
    if (g >= NH * NTOK * NTOK) return;
    int h = g / (NTOK * NTOK);
    int r = g % (NTOK * NTOK);
    int n = r / NTOK, m = r % NTOK;
    int dr = n / WSD - m / WSD + 11;
    int dc = n % WSD - m % WSD + 11;
    float v = g_tab[(dr * 23 + dc) * NH + h];
    g_bias[g] = 16.0f / (1.0f + expf(-v));
}

// ================= tensor-core attention: one CTA per (b,h) =================
#define SST 148
#define OFF_R 85248
#define QHI_O 0
#define QLO_O 11520
#define KHI_O 23040
#define KLO_O 34560
#define PSTR 304
#define PHI_O 0
#define PLO_O 43776
#define OFF_V 172800
#define VHI_O 0
#define VLO_O 11520
#define OFF_SUM 195840
#define ATTN_SMEM 196416

__global__ __launch_bounds__(256, 1) void attn_mma_kernel(
    const float* __restrict__ mask, const float* __restrict__ logit_scale) {
    extern __shared__ char smc[];
    float* Ssm  = (float*)smc;
    float* rsum = (float*)(smc + OFF_SUM);
    uint32_t sb = smem_u32(smc);

    int bh = blockIdx.x;
    int b = bh / NH, h = bh - b * NH;
    int w = b & 3;
    const float* gq = g_q + (size_t)bh * NTOK * HD;
    const float* gk = g_k + (size_t)bh * NTOK * HD;
    const float* gv = g_v + (size_t)bh * NTOK * HD;
    int tid = threadIdx.x, wid = tid >> 5, lane = tid & 31;

    float sc = expf(fminf(logit_scale[h], 4.6051702f));  // ln(100)

    if (tid < NTOK) {
        {
            const float4* p4 = (const float4*)(gq + tid * HD);
            float4 t[8]; float s = 0.f;
            #pragma unroll
            for (int i = 0; i < 8; i++) {
                t[i] = p4[i];
                s += t[i].x*t[i].x + t[i].y*t[i].y + t[i].z*t[i].z + t[i].w*t[i].w;
            }
            float qi = sc / fmaxf(sqrtf(s), 1e-12f);
            uint32_t* dh = (uint32_t*)(smc + OFF_R + QHI_O + tid * 80);
            uint32_t* dl = (uint32_t*)(smc + OFF_R + QLO_O + tid * 80);
            #pragma unroll
            for (int i = 0; i < 8; i++) {
                __nv_bfloat16 h0,l0,h1,l1,h2,l2,h3,l3;
                split1(t[i].x*qi, h0, l0); split1(t[i].y*qi, h1, l1);
                split1(t[i].z*qi, h2, l2); split1(t[i].w*qi, h3, l3);
                dh[2*i]   = pack2(h0, h1); dh[2*i+1] = pack2(h2, h3);
                dl[2*i]   = pack2(l0, l1); dl[2*i+1] = pack2(l2, l3);
            }
        }
        {
            const float4* p4 = (const float4*)(gk + tid * HD);
            float4 t[8]; float s = 0.f;
            #pragma unroll
            for (int i = 0; i < 8; i++) {
                t[i] = p4[i];
                s += t[i].x*t[i].x + t[i].y*t[i].y + t[i].z*t[i].z + t[i].w*t[i].w;
            }
            float ki = 1.0f / fmaxf(sqrtf(s), 1e-12f);
            uint32_t* dh = (uint32_t*)(smc + OFF_R + KHI_O + tid * 80);
            uint32_t* dl = (uint32_t*)(smc + OFF_R + KLO_O + tid * 80);
            #pragma unroll
            for (int i = 0; i < 8; i++) {
                __nv_bfloat16 h0,l0,h1,l1,h2,l2,h3,l3;
                split1(t[i].x*ki, h0, l0); split1(t[i].y*ki, h1, l1);
                split1(t[i].z*ki, h2, l2); split1(t[i].w*ki, h3, l3);
                dh[2*i]   = pack2(h0, h1); dh[2*i+1] = pack2(h2, h3);
                dl[2*i]   = pack2(l0, l1); dl[2*i+1] = pack2(l2, l3);
            }
        }
        {
            const float4* p4 = (const float4*)(gv + tid * HD);
            uint32_t* dh = (uint32_t*)(smc + OFF_V + VHI_O + tid * 80);
            uint32_t* dl = (uint32_t*)(smc + OFF_V + VLO_O + tid * 80);
            #pragma unroll
            for (int i = 0; i < 8; i++) {
                float4 t = p4[i];
                __nv_bfloat16 h0,l0,h1,l1,h2,l2,h3,l3;
                split1(t.x, h0, l0); split1(t.y, h1, l1);
                split1(t.z, h2, l2); split1(t.w, h3, l3);
                dh[2*i]   = pack2(h0, h1); dh[2*i+1] = pack2(h2, h3);
                dl[2*i]   = pack2(l0, l1); dl[2*i+1] = pack2(l2, l3);
            }
        }
    }
    __syncthreads();

    // ---- S = Q' K'^T + bias + mask ----
    const float* bi = g_bias + (size_t)h * NTOK * NTOK;
    const float* mk = mask + (size_t)w * NTOK * NTOK;
    uint32_t a_lane = (uint32_t)((lane & 15) * 80 + ((lane >> 4) & 1) * 16);
    uint32_t b_lane = (uint32_t)(((lane & 7) + ((lane & 16) >> 1)) * 80 + ((lane & 8) << 1));

    for (int u = wid; u < 81; u += 8) {
        int mt = u / 9, np = u - mt * 9;
        float c[8] = {};
        #pragma unroll
        for (int ks = 0; ks < 2; ks++) {
            uint32_t ah[4], al[4], bh_[4], bl_[4];
            uint32_t abase = sb + OFF_R + (uint32_t)(mt * 16 * 80) + a_lane + (uint32_t)(ks * 32);
            uint32_t bbase = sb + OFF_R + (uint32_t)(np * 16 * 80) + b_lane + (uint32_t)(ks * 32);
            ldsm4(ah,  abase + QHI_O);
            ldsm4(al,  abase + QLO_O);
            ldsm4(bh_, bbase + KHI_O);
            ldsm4(bl_, bbase + KLO_O);
            mma16816(c,     ah, &bh_[0]);
            mma16816(c + 4, ah, &bh_[2]);
            mma16816(c,     ah, &bl_[0]);
            mma16816(c + 4, ah, &bl_[2]);
            mma16816(c,     al, &bh_[0]);
            mma16816(c + 4, al, &bh_[2]);
        }
        int r0 = mt * 16 + (lane >> 2);
        int c0 = np * 16 + ((lane & 3) << 1);
        #pragma unroll
        for (int half = 0; half < 2; half++) {
            int r = r0 + half * 8;
            #pragma unroll
            for (int nt = 0; nt < 2; nt++) {
                int cc = c0 + nt * 8;
                float2 bv = *(const float2*)(bi + r * NTOK + cc);
                float2 mv = *(const float2*)(mk + r * NTOK + cc);
                Ssm[r * SST + cc]     = c[nt*4 + 2*half]     + bv.x + mv.x;
                Ssm[r * SST + cc + 1] = c[nt*4 + 2*half + 1] + bv.y + mv.y;
            }
        }
    }
    __syncthreads();

    // ---- softmax rows; emit unnormalized exp(P) as bf16 hi/lo ----
    if (tid < NTOK) {
        const float* srow = Ssm + tid * SST;
        float mx = -1e30f;
        for (int cc = 0; cc < NTOK; cc++) mx = fmaxf(mx, srow[cc]);
        float s = 0.f;
        uint32_t* ph = (uint32_t*)(smc + OFF_R + PHI_O + tid * PSTR);
        uint32_t* pl = (uint32_t*)(smc + OFF_R + PLO_O + tid * PSTR);
        for (int cc = 0; cc < NTOK; cc += 2) {
            float e0 = __expf(srow[cc]     - mx);
            float e1 = __expf(srow[cc + 1] - mx);
            s += e0 + e1;
            __nv_bfloat16 h0,l0,h1,l1;
            split1(e0, h0, l0); split1(e1, h1, l1);
            ph[cc >> 1] = pack2(h0, h1);
            pl[cc >> 1] = pack2(l0, l1);
        }
        rsum[tid] = 1.0f / s;
    }
    __syncthreads();

    // ---- O = P V ----
    uint32_t pa_lane = (uint32_t)((lane & 15) * PSTR + ((lane >> 4) & 1) * 16);
    uint32_t vb_lane = (uint32_t)((lane & 15) * 80 + ((lane >> 4) & 1) * 16);

    for (int u = wid; u < 18; u += 8) {
        int mt = u >> 1, np = u & 1;
        float c[8] = {};
        #pragma unroll
        for (int ks = 0; ks < 9; ks++) {
            uint32_t pa[4], pb[4], va[4], vb[4];
            uint32_t pbase = sb + OFF_R + (uint32_t)(mt * 16 * PSTR) + pa_lane + (uint32_t)(ks * 32);
            uint32_t vbase = sb + OFF_V + (uint32_t)(ks * 16 * 80) + (uint32_t)(np * 32) + vb_lane;
            ldsm4(pa, pbase + PHI_O);
            ldsm4(pb, pbase + PLO_O);
            ldsm4t(va, vbase + VHI_O);
            ldsm4t(vb, vbase + VLO_O);
            mma16816(c,     pa, &va[0]);
            mma16816(c + 4, pa, &va[2]);
            mma16816(c,     pa, &vb[0]);
            mma16816(c + 4, pa, &vb[2]);
            mma16816(c,     pb, &va[0]);
            mma16816(c + 4, pb, &va[2]);
        }
        int r0 = mt * 16 + (lane >> 2);
        int d0 = np * 16 + ((lane & 3) << 1);
        #pragma unroll
        for (int half = 0; half < 2; half++) {
            int r = r0 + half * 8;
            float ri = rsum[r];
            size_t rowo = ((size_t)b * NTOK + r) * CDIM + h * HD;
            #pragma unroll
            for (int nt = 0; nt < 2; nt++) {
                int d = d0 + nt * 8;
                float v0 = c[nt*4 + 2*half]     * ri;
                float v1 = c[nt*4 + 2*half + 1] * ri;
                __half h0,l0,h1,l1;
                split1h(v0, h0, l0); split1h(v1, h1, l1);
                *(uint32_t*)(g_aohi + rowo + d) = pack2h(h0, h1);
                *(uint32_t*)(g_aolo + rowo + d) = pack2h(l0, l1);
            }
        }
    }
}

// ---------------- launcher ----------------
extern "C" void kernel_launch(void* const* d_in, const int* in_sizes, int n_in,
                              void* d_out, int out_size) {
    const float* x           = (const float*)d_in[0];
    const float* mask        = (const float*)d_in[1];
    const float* qkv_w       = (const float*)d_in[2];
    const float* qkv_b       = (const float*)d_in[3];
    const float* logit_scale = (const float*)d_in[4];
    const float* cpb_w1      = (const float*)d_in[5];
    const float* cpb_b1      = (const float*)d_in[6];
    const float* cpb_w2      = (const float*)d_in[7];
    const float* proj_w      = (const float*)d_in[8];
    const float* proj_b      = (const float*)d_in[9];
    float* out = (float*)d_out;

    cudaFuncSetAttribute(attn_mma_kernel, cudaFuncAttributeMaxDynamicSharedMemorySize, ATTN_SMEM);
    cudaFuncSetAttribute(mma_gemm_kernel, cudaFuncAttributeMaxDynamicSharedMemorySize, GEMM_SMEM);

    __half *p_xhi, *p_xlo, *p_wqhi, *p_wphi, *p_aohi, *p_aolo;
    cudaGetSymbolAddress((void**)&p_xhi, g_xhi);
    cudaGetSymbolAddress((void**)&p_xlo, g_xlo);
    cudaGetSymbolAddress((void**)&p_wqhi, g_wqhi);
    cudaGetSymbolAddress((void**)&p_wphi, g_wphi);
    cudaGetSymbolAddress((void**)&p_aohi, g_aohi);
    cudaGetSymbolAddress((void**)&p_aolo, g_aolo);

    conv_split_kernel<<<(MROWS*CDIM/4 + 255)/256, 256>>>(x, p_xhi, p_xlo, MROWS*CDIM/4);
    conv_split_kernel<<<(3*CDIM*CDIM/4 + 255)/256, 256>>>(qkv_w, p_wqhi, nullptr, 3*CDIM*CDIM/4);
    conv_split_kernel<<<(CDIM*CDIM/4 + 255)/256, 256>>>(proj_w, p_wphi, nullptr, CDIM*CDIM/4);
    bias_tab_kernel<<<529, 512>>>(cpb_w1, cpb_b1, cpb_w2);
    bias_gather_kernel<<<(NH*NTOK*NTOK + 255)/256, 256>>>();
    // QKV: C[73728, 1152] = x @ qkv_w^T + qkv_b -> scatter q/k/v
    mma_gemm_kernel<<<dim3(9, 576), 256, GEMM_SMEM>>>(p_xhi, p_xlo, p_wqhi, qkv_b, nullptr, 1);
    attn_mma_kernel<<<BWIN*NH, 256, ATTN_SMEM>>>(mask, logit_scale);
    // proj: out[73728, 384] = attout @ proj_w^T + proj_b
    mma_gemm_kernel<<<dim3(3, 576), 256, GEMM_SMEM>>>(p_aohi, p_aolo, p_wphi, proj_b, out, 0);
}